// round 1
// baseline (speedup 1.0000x reference)
#include <cuda_runtime.h>
#include <math.h>

#define BATCH 4
#define SEQ   2048
#define DIM   1024
#define NH    16
#define HD    64
#define MROWS (BATCH*SEQ)   // 8192
#define N3    (3*DIM)       // 3072

// ---------------- scratch (device globals; no runtime allocation) ----------
__device__ float g_h[MROWS * DIM];            // LayerNorm output
__device__ float g_q[BATCH * NH * SEQ * HD];  // [bh][t][d]
__device__ float g_k[BATCH * NH * SEQ * HD];
__device__ float g_v[BATCH * NH * SEQ * HD];
__device__ float g_o[MROWS * DIM];            // attention out in [B,N,D]

// ---------------- LayerNorm ------------------------------------------------
__global__ __launch_bounds__(256) void ln_kernel(const float* __restrict__ x,
                                                 const float* __restrict__ w,
                                                 const float* __restrict__ b) {
    int row = blockIdx.x;
    const float4 v = ((const float4*)(x + (size_t)row * DIM))[threadIdx.x];
    float s  = v.x + v.y + v.z + v.w;
    float ss = v.x*v.x + v.y*v.y + v.z*v.z + v.w*v.w;

    __shared__ float sh_s[8], sh_ss[8];
    #pragma unroll
    for (int o = 16; o > 0; o >>= 1) {
        s  += __shfl_xor_sync(0xffffffffu, s,  o);
        ss += __shfl_xor_sync(0xffffffffu, ss, o);
    }
    int wid = threadIdx.x >> 5, lid = threadIdx.x & 31;
    if (lid == 0) { sh_s[wid] = s; sh_ss[wid] = ss; }
    __syncthreads();
    if (wid == 0) {
        s  = (lid < 8) ? sh_s[lid]  : 0.0f;
        ss = (lid < 8) ? sh_ss[lid] : 0.0f;
        #pragma unroll
        for (int o = 4; o > 0; o >>= 1) {
            s  += __shfl_xor_sync(0xffffffffu, s,  o);
            ss += __shfl_xor_sync(0xffffffffu, ss, o);
        }
        if (lid == 0) { sh_s[0] = s; sh_ss[0] = ss; }
    }
    __syncthreads();
    float mean = sh_s[0] * (1.0f / DIM);
    float var  = sh_ss[0] * (1.0f / DIM) - mean * mean;
    float rstd = rsqrtf(var + 1e-5f);

    const float4 wv = ((const float4*)w)[threadIdx.x];
    const float4 bv = ((const float4*)b)[threadIdx.x];
    float4 o4;
    o4.x = (v.x - mean) * rstd * wv.x + bv.x;
    o4.y = (v.y - mean) * rstd * wv.y + bv.y;
    o4.z = (v.z - mean) * rstd * wv.z + bv.z;
    o4.w = (v.w - mean) * rstd * wv.w + bv.w;
    ((float4*)(g_h + (size_t)row * DIM))[threadIdx.x] = o4;
}

// ---------------- QKV GEMM: C = h @ W^T + b, scattered into q/k/v ----------
// 128x128x8 tiling, 256 threads, 8x8 per thread.
__global__ __launch_bounds__(256) void qkv_gemm(const float* __restrict__ W,
                                                const float* __restrict__ bias) {
    __shared__ float As[8][128];
    __shared__ float Bs[8][128];
    const int bx = blockIdx.x, by = blockIdx.y;
    const int tid = threadIdx.x, tx = tid & 15, ty = tid >> 4;

    const float* A  = g_h + (size_t)by * 128 * DIM;
    const float* Wp = W   + (size_t)bx * 128 * DIM;
    const int lrow = tid >> 1;
    const int lcol = (tid & 1) * 4;

    float acc[8][8];
    #pragma unroll
    for (int i = 0; i < 8; i++)
        #pragma unroll
        for (int j = 0; j < 8; j++) acc[i][j] = 0.0f;

    for (int k0 = 0; k0 < DIM; k0 += 8) {
        float4 a  = *(const float4*)(A  + (size_t)lrow * DIM + k0 + lcol);
        float4 w4 = *(const float4*)(Wp + (size_t)lrow * DIM + k0 + lcol);
        As[lcol+0][lrow] = a.x;  As[lcol+1][lrow] = a.y;
        As[lcol+2][lrow] = a.z;  As[lcol+3][lrow] = a.w;
        Bs[lcol+0][lrow] = w4.x; Bs[lcol+1][lrow] = w4.y;
        Bs[lcol+2][lrow] = w4.z; Bs[lcol+3][lrow] = w4.w;
        __syncthreads();
        #pragma unroll
        for (int k = 0; k < 8; k++) {
            float4 a0 = *(const float4*)&As[k][ty*8];
            float4 a1 = *(const float4*)&As[k][ty*8+4];
            float4 b0 = *(const float4*)&Bs[k][tx*8];
            float4 b1 = *(const float4*)&Bs[k][tx*8+4];
            float ar[8] = {a0.x,a0.y,a0.z,a0.w,a1.x,a1.y,a1.z,a1.w};
            float br[8] = {b0.x,b0.y,b0.z,b0.w,b1.x,b1.y,b1.z,b1.w};
            #pragma unroll
            for (int i = 0; i < 8; i++)
                #pragma unroll
                for (int j = 0; j < 8; j++)
                    acc[i][j] = fmaf(ar[i], br[j], acc[i][j]);
        }
        __syncthreads();
    }

    // epilogue: n -> (which, head, d); m -> (b, t); scatter into q/k/v
    #pragma unroll
    for (int j = 0; j < 8; j++) {
        int n = bx * 128 + tx * 8 + j;
        float bv = bias[n];
        int which = n >> 10;
        int hn = n & 1023;
        int head = hn >> 6, d = hn & 63;
        float* dst = (which == 0) ? g_q : (which == 1) ? g_k : g_v;
        #pragma unroll
        for (int i = 0; i < 8; i++) {
            int m = by * 128 + ty * 8 + i;
            int bb = m >> 11, t = m & 2047;
            dst[(((size_t)(bb * NH + head)) * SEQ + t) * HD + d] = acc[i][j] + bv;
        }
    }
}

// ---------------- per-head L2 normalize of q (×sqrt(hd)) and k --------------
__global__ __launch_bounds__(256) void norm_qk() {
    const int R = BATCH * NH * SEQ;
    int w = (blockIdx.x * blockDim.x + threadIdx.x) >> 5;
    int lane = threadIdx.x & 31;
    float* base = (w < R) ? g_q : g_k;
    float scale = (w < R) ? 8.0f : 1.0f;   // sqrt(HD)=8 folded into q
    int row = (w < R) ? w : (w - R);
    float2 v = ((float2*)(base + (size_t)row * HD))[lane];
    float ss = v.x * v.x + v.y * v.y;
    #pragma unroll
    for (int o = 16; o > 0; o >>= 1) ss += __shfl_xor_sync(0xffffffffu, ss, o);
    float rn = scale / fmaxf(sqrtf(ss), 1e-12f);
    v.x *= rn; v.y *= rn;
    ((float2*)(base + (size_t)row * HD))[lane] = v;
}

// ---------------- flash attention (fp32, 64-row q tile per block) ----------
// smem: Qt[d][r], Kt[d][j], Vs[j][d], Pt[j][r]  — each 64x64 floats.
__global__ __launch_bounds__(256) void flash_kernel() {
    extern __shared__ float sm[];
    float* Qt = sm;
    float* Kt = sm + 4096;
    float* Vs = sm + 8192;
    float* Pt = sm + 12288;

    const int bh = blockIdx.y;
    const int q0 = blockIdx.x * 64;
    const int tid = threadIdx.x, tx = tid & 15, ty = tid >> 4;

    const float* qbase = g_q + ((size_t)bh * SEQ + q0) * HD;
    const float* kbase = g_k + (size_t)bh * SEQ * HD;
    const float* vbase = g_v + (size_t)bh * SEQ * HD;

    // load Q tile transposed (d-major)
    #pragma unroll
    for (int t = 0; t < 4; t++) {
        int f = tid + t * 256;          // float4 id, 0..1023
        int r = f >> 4, d4 = (f & 15) * 4;
        float4 qv = *(const float4*)(qbase + r * HD + d4);
        Qt[(d4+0)*64 + r] = qv.x;
        Qt[(d4+1)*64 + r] = qv.y;
        Qt[(d4+2)*64 + r] = qv.z;
        Qt[(d4+3)*64 + r] = qv.w;
    }

    float m_i[4], l_i[4], o_acc[4][4];
    #pragma unroll
    for (int i = 0; i < 4; i++) {
        m_i[i] = -1e30f; l_i[i] = 0.0f;
        #pragma unroll
        for (int j = 0; j < 4; j++) o_acc[i][j] = 0.0f;
    }

    for (int kt = 0; kt < SEQ; kt += 64) {
        // load K (transposed) and V (direct)
        #pragma unroll
        for (int t = 0; t < 4; t++) {
            int f = tid + t * 256;
            int j = f >> 4, d4 = (f & 15) * 4;
            float4 kv = *(const float4*)(kbase + (size_t)(kt + j) * HD + d4);
            Kt[(d4+0)*64 + j] = kv.x;
            Kt[(d4+1)*64 + j] = kv.y;
            Kt[(d4+2)*64 + j] = kv.z;
            Kt[(d4+3)*64 + j] = kv.w;
            float4 vv = *(const float4*)(vbase + (size_t)(kt + j) * HD + d4);
            *(float4*)(Vs + j * 64 + d4) = vv;
        }
        __syncthreads();

        // S = Q @ K^T  (4x4 per thread)
        float s[4][4];
        #pragma unroll
        for (int i = 0; i < 4; i++)
            #pragma unroll
            for (int j = 0; j < 4; j++) s[i][j] = 0.0f;
        #pragma unroll
        for (int d = 0; d < 64; d++) {
            float4 qv = *(const float4*)(Qt + d * 64 + ty * 4);
            float4 kv = *(const float4*)(Kt + d * 64 + tx * 4);
            float qa[4] = {qv.x, qv.y, qv.z, qv.w};
            float ka[4] = {kv.x, kv.y, kv.z, kv.w};
            #pragma unroll
            for (int i = 0; i < 4; i++)
                #pragma unroll
                for (int j = 0; j < 4; j++)
                    s[i][j] = fmaf(qa[i], ka[j], s[i][j]);
        }

        // online softmax (row reduce across the 16 tx lanes)
        #pragma unroll
        for (int i = 0; i < 4; i++) {
            float rm = fmaxf(fmaxf(s[i][0], s[i][1]), fmaxf(s[i][2], s[i][3]));
            #pragma unroll
            for (int o = 8; o > 0; o >>= 1)
                rm = fmaxf(rm, __shfl_xor_sync(0xffffffffu, rm, o));
            float newm = fmaxf(m_i[i], rm);
            float alpha = __expf(m_i[i] - newm);
            float rs = 0.0f;
            #pragma unroll
            for (int j = 0; j < 4; j++) {
                s[i][j] = __expf(s[i][j] - newm);
                rs += s[i][j];
            }
            #pragma unroll
            for (int o = 8; o > 0; o >>= 1)
                rs += __shfl_xor_sync(0xffffffffu, rs, o);
            l_i[i] = l_i[i] * alpha + rs;
            m_i[i] = newm;
            #pragma unroll
            for (int j = 0; j < 4; j++) o_acc[i][j] *= alpha;
        }

        // write P transposed (j-major) for the O GEMM
        #pragma unroll
        for (int i = 0; i < 4; i++)
            #pragma unroll
            for (int j = 0; j < 4; j++)
                Pt[(tx * 4 + j) * 64 + ty * 4 + i] = s[i][j];
        __syncthreads();

        // O += P @ V
        #pragma unroll
        for (int j = 0; j < 64; j++) {
            float4 pv = *(const float4*)(Pt + j * 64 + ty * 4);
            float4 vv = *(const float4*)(Vs + j * 64 + tx * 4);
            float pa[4] = {pv.x, pv.y, pv.z, pv.w};
            float va[4] = {vv.x, vv.y, vv.z, vv.w};
            #pragma unroll
            for (int i = 0; i < 4; i++)
                #pragma unroll
                for (int jj = 0; jj < 4; jj++)
                    o_acc[i][jj] = fmaf(pa[i], va[jj], o_acc[i][jj]);
        }
        __syncthreads();
    }

    // epilogue: write [B, N, H*HD]
    const int b = bh >> 4, head = bh & 15;
    #pragma unroll
    for (int i = 0; i < 4; i++) {
        float inv = 1.0f / l_i[i];
        int r = ty * 4 + i;
        float4 ov;
        ov.x = o_acc[i][0] * inv; ov.y = o_acc[i][1] * inv;
        ov.z = o_acc[i][2] * inv; ov.w = o_acc[i][3] * inv;
        *(float4*)(g_o + ((size_t)(b * SEQ + q0 + r)) * DIM + head * 64 + tx * 4) = ov;
    }
}

// ---------------- output projection + residual ------------------------------
__global__ __launch_bounds__(256) void out_gemm(const float* __restrict__ W,
                                                const float* __restrict__ bias,
                                                const float* __restrict__ x,
                                                float* __restrict__ y) {
    __shared__ float As[8][128];
    __shared__ float Bs[8][128];
    const int bx = blockIdx.x, by = blockIdx.y;
    const int tid = threadIdx.x, tx = tid & 15, ty = tid >> 4;

    const float* A  = g_o + (size_t)by * 128 * DIM;
    const float* Wp = W   + (size_t)bx * 128 * DIM;
    const int lrow = tid >> 1;
    const int lcol = (tid & 1) * 4;

    float acc[8][8];
    #pragma unroll
    for (int i = 0; i < 8; i++)
        #pragma unroll
        for (int j = 0; j < 8; j++) acc[i][j] = 0.0f;

    for (int k0 = 0; k0 < DIM; k0 += 8) {
        float4 a  = *(const float4*)(A  + (size_t)lrow * DIM + k0 + lcol);
        float4 w4 = *(const float4*)(Wp + (size_t)lrow * DIM + k0 + lcol);
        As[lcol+0][lrow] = a.x;  As[lcol+1][lrow] = a.y;
        As[lcol+2][lrow] = a.z;  As[lcol+3][lrow] = a.w;
        Bs[lcol+0][lrow] = w4.x; Bs[lcol+1][lrow] = w4.y;
        Bs[lcol+2][lrow] = w4.z; Bs[lcol+3][lrow] = w4.w;
        __syncthreads();
        #pragma unroll
        for (int k = 0; k < 8; k++) {
            float4 a0 = *(const float4*)&As[k][ty*8];
            float4 a1 = *(const float4*)&As[k][ty*8+4];
            float4 b0 = *(const float4*)&Bs[k][tx*8];
            float4 b1 = *(const float4*)&Bs[k][tx*8+4];
            float ar[8] = {a0.x,a0.y,a0.z,a0.w,a1.x,a1.y,a1.z,a1.w};
            float br[8] = {b0.x,b0.y,b0.z,b0.w,b1.x,b1.y,b1.z,b1.w};
            #pragma unroll
            for (int i = 0; i < 8; i++)
                #pragma unroll
                for (int j = 0; j < 8; j++)
                    acc[i][j] = fmaf(ar[i], br[j], acc[i][j]);
        }
        __syncthreads();
    }

    #pragma unroll
    for (int i = 0; i < 8; i++) {
        int m = by * 128 + ty * 8 + i;
        #pragma unroll
        for (int j = 0; j < 8; j++) {
            int n = bx * 128 + tx * 8 + j;
            y[(size_t)m * DIM + n] = acc[i][j] + bias[n] + x[(size_t)m * DIM + n];
        }
    }
}

// ---------------- launch -----------------------------------------------------
extern "C" void kernel_launch(void* const* d_in, const int* in_sizes, int n_in,
                              void* d_out, int out_size) {
    const float* x     = (const float*)d_in[0];
    const float* ln_w  = (const float*)d_in[1];
    const float* ln_b  = (const float*)d_in[2];
    const float* qkv_w = (const float*)d_in[3];
    const float* qkv_b = (const float*)d_in[4];
    const float* out_w = (const float*)d_in[5];
    const float* out_b = (const float*)d_in[6];
    float* y = (float*)d_out;

    ln_kernel<<<MROWS, 256>>>(x, ln_w, ln_b);

    qkv_gemm<<<dim3(N3 / 128, MROWS / 128), 256>>>(qkv_w, qkv_b);

    norm_qk<<<(2 * BATCH * NH * SEQ) / 8, 256>>>();

    cudaFuncSetAttribute(flash_kernel,
                         cudaFuncAttributeMaxDynamicSharedMemorySize, 65536);
    flash_kernel<<<dim3(SEQ / 64, BATCH * NH), 256, 65536>>>();

    out_gemm<<<dim3(DIM / 128, MROWS / 128), 256>>>(out_w, out_b, x, y);
}

// round 5
// speedup vs baseline: 3.3795x; 3.3795x over previous
#include <cuda_runtime.h>
#include <math.h>

#define BATCH 4
#define SEQ   2048
#define DIM   1024
#define NH    16
#define HD    64
#define MROWS (BATCH*SEQ)   // 8192
#define N3    (3*DIM)       // 3072

// ---------------- scratch (device globals; no runtime allocation) ----------
// NOTE: referenced ONLY from device code. Passing these as kernel args from
// host passes the host-side shadow address (silently readable on GB300 via
// ATS -> reads zeros). That was the round 2-4 bug.
__device__ float g_h[MROWS * DIM];            // LayerNorm output (tf32-rounded)
__device__ float g_q[BATCH * NH * SEQ * HD];  // [bh][t][d]
__device__ float g_k[BATCH * NH * SEQ * HD];
__device__ float g_v[BATCH * NH * SEQ * HD];
__device__ float g_o[MROWS * DIM];            // attention out (tf32-rounded)

// ---------------- tf32 helpers ----------------------------------------------
__device__ __forceinline__ float tf32r(float x) {
    unsigned u;
    asm("cvt.rna.tf32.f32 %0, %1;" : "=r"(u) : "f"(x));
    return __uint_as_float(u);
}

// D += A(16x8, row) * B(8x8, col), tf32 inputs in fp32 containers, fp32 accum.
// Fragment layout (lane = 4g + j), per CUTLASS SM80_16x8x8_F32TF32TF32F32_TN:
//   a0=(g, ka), a1=(g+8, ka), a2=(g, kb), a3=(g+8, kb)   [ka=j, kb=j+4]
//   b0=(ka, n=g), b1=(kb, n=g)
//   c0=(g,2j), c1=(g,2j+1), c2=(g+8,2j), c3=(g+8,2j+1)
__device__ __forceinline__ void mma8(float4& d, const float a[4], float b0, float b1) {
    asm volatile(
        "mma.sync.aligned.m16n8k8.row.col.f32.tf32.tf32.f32 "
        "{%0,%1,%2,%3}, {%4,%5,%6,%7}, {%8,%9}, {%0,%1,%2,%3};\n"
        : "+f"(d.x), "+f"(d.y), "+f"(d.z), "+f"(d.w)
        : "r"(__float_as_uint(a[0])), "r"(__float_as_uint(a[1])),
          "r"(__float_as_uint(a[2])), "r"(__float_as_uint(a[3])),
          "r"(__float_as_uint(b0)),  "r"(__float_as_uint(b1)));
}

// ---------------- LayerNorm (outputs tf32-rounded) --------------------------
__global__ __launch_bounds__(256) void ln_kernel(const float* __restrict__ x,
                                                 const float* __restrict__ w,
                                                 const float* __restrict__ b) {
    int row = blockIdx.x;
    const float4 v = ((const float4*)(x + (size_t)row * DIM))[threadIdx.x];
    float s  = v.x + v.y + v.z + v.w;
    float ss = v.x*v.x + v.y*v.y + v.z*v.z + v.w*v.w;

    __shared__ float sh_s[8], sh_ss[8];
    #pragma unroll
    for (int o = 16; o > 0; o >>= 1) {
        s  += __shfl_xor_sync(0xffffffffu, s,  o);
        ss += __shfl_xor_sync(0xffffffffu, ss, o);
    }
    int wid = threadIdx.x >> 5, lid = threadIdx.x & 31;
    if (lid == 0) { sh_s[wid] = s; sh_ss[wid] = ss; }
    __syncthreads();
    if (wid == 0) {
        s  = (lid < 8) ? sh_s[lid]  : 0.0f;
        ss = (lid < 8) ? sh_ss[lid] : 0.0f;
        #pragma unroll
        for (int o = 4; o > 0; o >>= 1) {
            s  += __shfl_xor_sync(0xffffffffu, s,  o);
            ss += __shfl_xor_sync(0xffffffffu, ss, o);
        }
        if (lid == 0) { sh_s[0] = s; sh_ss[0] = ss; }
    }
    __syncthreads();
    float mean = sh_s[0] * (1.0f / DIM);
    float var  = sh_ss[0] * (1.0f / DIM) - mean * mean;
    float rstd = rsqrtf(var + 1e-5f);

    const float4 wv = ((const float4*)w)[threadIdx.x];
    const float4 bv = ((const float4*)b)[threadIdx.x];
    float4 o4;
    o4.x = tf32r((v.x - mean) * rstd * wv.x + bv.x);
    o4.y = tf32r((v.y - mean) * rstd * wv.y + bv.y);
    o4.z = tf32r((v.z - mean) * rstd * wv.z + bv.z);
    o4.w = tf32r((v.w - mean) * rstd * wv.w + bv.w);
    ((float4*)(g_h + (size_t)row * DIM))[threadIdx.x] = o4;
}

// ---------------- tensor-core GEMM: C = A @ W^T (+epilogue) -----------------
// 128x128 block tile, 8 warps (4m x 2n), warp tile 32x64, k-tile 32.
// MODE 0: A=g_h, qkv scatter epilogue (+bias). MODE 1: A=g_o, y = C + bias + x.
__device__ __forceinline__ void scatter_qkv(int m, int n, float val) {
    int which = n >> 10;
    int hn = n & 1023;
    int head = hn >> 6, d = hn & 63;
    float* dst = (which == 0) ? g_q : (which == 1) ? g_k : g_v;
    int bb = m >> 11, t = m & 2047;
    dst[(((size_t)(bb * NH + head)) * SEQ + t) * HD + d] = val;
}

template<int MODE>
__global__ __launch_bounds__(256) void gemm_tc(const float* __restrict__ W,
                                               const float* __restrict__ bias,
                                               const float* __restrict__ x,
                                               float* __restrict__ y) {
    const float* A = (MODE == 0) ? g_h : g_o;   // device-side symbol reference!
    __shared__ float As[128 * 36];
    __shared__ float Bs[128 * 36];
    const int tid = threadIdx.x;
    const int w = tid >> 5, lane = tid & 31;
    const int g = lane >> 2, j = lane & 3;
    const int wm = w & 3, wn = w >> 2;          // warp 32-row slot, 64-col slot
    const int m0 = blockIdx.y * 128;
    const int n0 = blockIdx.x * 128;

    const float* Ap = A + (size_t)m0 * DIM;
    const float* Wp = W + (size_t)n0 * DIM;

    float4 c[2][8];
    #pragma unroll
    for (int mt = 0; mt < 2; mt++)
        #pragma unroll
        for (int nt = 0; nt < 8; nt++) c[mt][nt] = make_float4(0.f, 0.f, 0.f, 0.f);

    // prefetch k0=0
    float4 ra[4], rb[4];
    #pragma unroll
    for (int t = 0; t < 4; t++) {
        int id = tid + 256 * t; int r = id >> 3; int c4 = (id & 7) * 4;
        ra[t] = *(const float4*)(Ap + (size_t)r * DIM + c4);
        rb[t] = *(const float4*)(Wp + (size_t)r * DIM + c4);
    }

    for (int k0 = 0; k0 < DIM; k0 += 32) {
        #pragma unroll
        for (int t = 0; t < 4; t++) {
            int id = tid + 256 * t; int r = id >> 3; int c4 = (id & 7) * 4;
            *(float4*)(&As[r * 36 + c4]) = ra[t];           // A pre-rounded
            float4 bb4;
            bb4.x = tf32r(rb[t].x); bb4.y = tf32r(rb[t].y);
            bb4.z = tf32r(rb[t].z); bb4.w = tf32r(rb[t].w);
            *(float4*)(&Bs[r * 36 + c4]) = bb4;
        }
        __syncthreads();

        if (k0 + 32 < DIM) {
            #pragma unroll
            for (int t = 0; t < 4; t++) {
                int id = tid + 256 * t; int r = id >> 3; int c4 = (id & 7) * 4;
                ra[t] = *(const float4*)(Ap + (size_t)r * DIM + k0 + 32 + c4);
                rb[t] = *(const float4*)(Wp + (size_t)r * DIM + k0 + 32 + c4);
            }
        }

        #pragma unroll
        for (int kk = 0; kk < 4; kk++) {
            float a[2][4];
            #pragma unroll
            for (int mt = 0; mt < 2; mt++) {
                int row = wm * 32 + mt * 16 + g;
                a[mt][0] = As[row * 36 + kk * 8 + j];          // (g,   ka)
                a[mt][1] = As[(row + 8) * 36 + kk * 8 + j];    // (g+8, ka)
                a[mt][2] = As[row * 36 + kk * 8 + j + 4];      // (g,   kb)
                a[mt][3] = As[(row + 8) * 36 + kk * 8 + j + 4];// (g+8, kb)
            }
            float b0[8], b1[8];
            #pragma unroll
            for (int nt = 0; nt < 8; nt++) {
                int n = wn * 64 + nt * 8 + g;
                b0[nt] = Bs[n * 36 + kk * 8 + j];              // (ka, n)
                b1[nt] = Bs[n * 36 + kk * 8 + j + 4];          // (kb, n)
            }
            #pragma unroll
            for (int mt = 0; mt < 2; mt++)
                #pragma unroll
                for (int nt = 0; nt < 8; nt++)
                    mma8(c[mt][nt], a[mt], b0[nt], b1[nt]);
        }
        __syncthreads();
    }

    // epilogue
    #pragma unroll
    for (int mt = 0; mt < 2; mt++) {
        int r0 = m0 + wm * 32 + mt * 16 + g;
        int r1 = r0 + 8;
        #pragma unroll
        for (int nt = 0; nt < 8; nt++) {
            int n = n0 + wn * 64 + nt * 8 + 2 * j;
            float bv0 = bias[n], bv1 = bias[n + 1];
            if (MODE == 0) {
                scatter_qkv(r0, n,     c[mt][nt].x + bv0);
                scatter_qkv(r0, n + 1, c[mt][nt].y + bv1);
                scatter_qkv(r1, n,     c[mt][nt].z + bv0);
                scatter_qkv(r1, n + 1, c[mt][nt].w + bv1);
            } else {
                y[(size_t)r0 * DIM + n]     = c[mt][nt].x + bv0 + x[(size_t)r0 * DIM + n];
                y[(size_t)r0 * DIM + n + 1] = c[mt][nt].y + bv1 + x[(size_t)r0 * DIM + n + 1];
                y[(size_t)r1 * DIM + n]     = c[mt][nt].z + bv0 + x[(size_t)r1 * DIM + n];
                y[(size_t)r1 * DIM + n + 1] = c[mt][nt].w + bv1 + x[(size_t)r1 * DIM + n + 1];
            }
        }
    }
}

// ---------------- per-head L2 normalize of q (×sqrt(hd)) and k --------------
__global__ __launch_bounds__(256) void norm_qk() {
    const int R = BATCH * NH * SEQ;
    int w = (blockIdx.x * blockDim.x + threadIdx.x) >> 5;
    int lane = threadIdx.x & 31;
    float* base = (w < R) ? g_q : g_k;
    float scale = (w < R) ? 8.0f : 1.0f;   // sqrt(HD)=8 folded into q
    int row = (w < R) ? w : (w - R);
    float2 v = ((float2*)(base + (size_t)row * HD))[lane];
    float ss = v.x * v.x + v.y * v.y;
    #pragma unroll
    for (int o = 16; o > 0; o >>= 1) ss += __shfl_xor_sync(0xffffffffu, ss, o);
    float rn = scale / fmaxf(sqrtf(ss), 1e-12f);
    v.x *= rn; v.y *= rn;
    ((float2*)(base + (size_t)row * HD))[lane] = v;
}

// ---------------- flash attention, tensor-core tf32 -------------------------
// 128-row Q tile, 32-key K tile, 8 warps; warp w owns Q rows [w*16, w*16+16).
// STATIC shared memory, 35.8 KB total — no opt-in attribute needed.
#define KT        32
#define KS_STRIDE 68
#define VS_STRIDE 68
#define PS_STRIDE 36

__global__ __launch_bounds__(256) void flash_tc() {
    __shared__ float Ks[KT * KS_STRIDE];   //  8704 B
    __shared__ float Vs[KT * VS_STRIDE];   //  8704 B
    __shared__ float Ps[128 * PS_STRIDE];  // 18432 B

    const int tid = threadIdx.x, w = tid >> 5, lane = tid & 31;
    const int g = lane >> 2, j = lane & 3;
    const int bh = blockIdx.y;
    const int q0 = blockIdx.x * 128;

    const float* qbase = g_q + ((size_t)bh * SEQ + q0) * HD;
    const float* kbase = g_k + (size_t)bh * SEQ * HD;
    const float* vbase = g_v + (size_t)bh * SEQ * HD;

    // persistent Q fragments for this warp's 16 rows
    float qa[8][4];
    {
        const float* qr  = qbase + (size_t)(w * 16 + g) * HD;
        const float* qr8 = qr + 8 * HD;
        #pragma unroll
        for (int kk = 0; kk < 8; kk++) {
            qa[kk][0] = tf32r(qr [kk * 8 + j]);        // (g,   ka)
            qa[kk][1] = tf32r(qr8[kk * 8 + j]);        // (g+8, ka)
            qa[kk][2] = tf32r(qr [kk * 8 + j + 4]);    // (g,   kb)
            qa[kk][3] = tf32r(qr8[kk * 8 + j + 4]);    // (g+8, kb)
        }
    }

    float4 o[8];
    #pragma unroll
    for (int nt = 0; nt < 8; nt++) o[nt] = make_float4(0.f, 0.f, 0.f, 0.f);
    float m0r = -1e30f, m1r = -1e30f, l0 = 0.f, l1 = 0.f;

    const int pr  = (w * 16 + g) * PS_STRIDE;
    const int pr8 = pr + 8 * PS_STRIDE;

    for (int kt = 0; kt < SEQ; kt += KT) {
        // load K,V tiles (tf32-rounded); 512 float4 per tensor, 2 per thread
        #pragma unroll
        for (int t = 0; t < 2; t++) {
            int id = tid + 256 * t; int r = id >> 4; int c4 = (id & 15) * 4;
            float4 kv = *(const float4*)(kbase + (size_t)(kt + r) * HD + c4);
            float4 k4; k4.x = tf32r(kv.x); k4.y = tf32r(kv.y);
                       k4.z = tf32r(kv.z); k4.w = tf32r(kv.w);
            *(float4*)(&Ks[r * KS_STRIDE + c4]) = k4;
            float4 vv = *(const float4*)(vbase + (size_t)(kt + r) * HD + c4);
            float4 v4; v4.x = tf32r(vv.x); v4.y = tf32r(vv.y);
                       v4.z = tf32r(vv.z); v4.w = tf32r(vv.w);
            *(float4*)(&Vs[r * VS_STRIDE + c4]) = v4;
        }
        __syncthreads();

        // S = Q @ K^T   (per warp: 16 x 32)
        float4 s[4];
        #pragma unroll
        for (int nt = 0; nt < 4; nt++) s[nt] = make_float4(0.f, 0.f, 0.f, 0.f);
        #pragma unroll
        for (int nt = 0; nt < 4; nt++) {
            int kb = (nt * 8 + g) * KS_STRIDE;
            #pragma unroll
            for (int kk = 0; kk < 8; kk++) {
                float b0 = Ks[kb + kk * 8 + j];        // (ka, n)
                float b1 = Ks[kb + kk * 8 + j + 4];    // (kb, n)
                mma8(s[nt], qa[kk], b0, b1);
            }
        }

        // online softmax: rows (g) in .x/.y, (g+8) in .z/.w
        float rm0 = -1e30f, rm1 = -1e30f;
        #pragma unroll
        for (int nt = 0; nt < 4; nt++) {
            rm0 = fmaxf(rm0, fmaxf(s[nt].x, s[nt].y));
            rm1 = fmaxf(rm1, fmaxf(s[nt].z, s[nt].w));
        }
        #pragma unroll
        for (int off = 1; off <= 2; off <<= 1) {
            rm0 = fmaxf(rm0, __shfl_xor_sync(0xffffffffu, rm0, off));
            rm1 = fmaxf(rm1, __shfl_xor_sync(0xffffffffu, rm1, off));
        }
        float nm0 = fmaxf(m0r, rm0), nm1 = fmaxf(m1r, rm1);
        float al0 = __expf(m0r - nm0), al1 = __expf(m1r - nm1);
        float rs0 = 0.f, rs1 = 0.f;
        #pragma unroll
        for (int nt = 0; nt < 4; nt++) {
            s[nt].x = __expf(s[nt].x - nm0);
            s[nt].y = __expf(s[nt].y - nm0);
            s[nt].z = __expf(s[nt].z - nm1);
            s[nt].w = __expf(s[nt].w - nm1);
            rs0 += s[nt].x + s[nt].y;
            rs1 += s[nt].z + s[nt].w;
        }
        #pragma unroll
        for (int off = 1; off <= 2; off <<= 1) {
            rs0 += __shfl_xor_sync(0xffffffffu, rs0, off);
            rs1 += __shfl_xor_sync(0xffffffffu, rs1, off);
        }
        l0 = l0 * al0 + rs0;
        l1 = l1 * al1 + rs1;
        m0r = nm0; m1r = nm1;
        #pragma unroll
        for (int nt = 0; nt < 8; nt++) {
            o[nt].x *= al0; o[nt].y *= al0;
            o[nt].z *= al1; o[nt].w *= al1;
        }

        // write P (tf32-rounded) — same warp reads it back, so only syncwarp
        #pragma unroll
        for (int nt = 0; nt < 4; nt++) {
            int col = nt * 8 + 2 * j;
            float2 p0 = make_float2(tf32r(s[nt].x), tf32r(s[nt].y));
            float2 p1 = make_float2(tf32r(s[nt].z), tf32r(s[nt].w));
            *(float2*)(&Ps[pr  + col]) = p0;
            *(float2*)(&Ps[pr8 + col]) = p1;
        }
        __syncwarp();

        // O += P @ V
        #pragma unroll
        for (int kk = 0; kk < 4; kk++) {
            float a[4];
            a[0] = Ps[pr  + kk * 8 + j];       // (g,   ka)
            a[1] = Ps[pr8 + kk * 8 + j];       // (g+8, ka)
            a[2] = Ps[pr  + kk * 8 + j + 4];   // (g,   kb)
            a[3] = Ps[pr8 + kk * 8 + j + 4];   // (g+8, kb)
            int vb0 = (kk * 8 + j) * VS_STRIDE;
            int vb1 = (kk * 8 + j + 4) * VS_STRIDE;
            #pragma unroll
            for (int nt = 0; nt < 8; nt++) {
                float b0 = Vs[vb0 + nt * 8 + g];
                float b1 = Vs[vb1 + nt * 8 + g];
                mma8(o[nt], a, b0, b1);
            }
        }
        __syncthreads();
    }

    // epilogue: rescale by 1/l, write g_o [B, N, H*HD] tf32-rounded
    float inv0 = 1.0f / l0, inv1 = 1.0f / l1;
    const int b = bh >> 4, head = bh & 15;
    size_t row0 = ((size_t)(b * SEQ + q0 + w * 16 + g)) * DIM + head * 64;
    size_t row1 = row0 + (size_t)8 * DIM;
    #pragma unroll
    for (int nt = 0; nt < 8; nt++) {
        int col = nt * 8 + 2 * j;
        float2 o0 = make_float2(tf32r(o[nt].x * inv0), tf32r(o[nt].y * inv0));
        float2 o1 = make_float2(tf32r(o[nt].z * inv1), tf32r(o[nt].w * inv1));
        *(float2*)(&g_o[row0 + col]) = o0;
        *(float2*)(&g_o[row1 + col]) = o1;
    }
}

// ---------------- launch -----------------------------------------------------
extern "C" void kernel_launch(void* const* d_in, const int* in_sizes, int n_in,
                              void* d_out, int out_size) {
    const float* x     = (const float*)d_in[0];
    const float* ln_w  = (const float*)d_in[1];
    const float* ln_b  = (const float*)d_in[2];
    const float* qkv_w = (const float*)d_in[3];
    const float* qkv_b = (const float*)d_in[4];
    const float* out_w = (const float*)d_in[5];
    const float* out_b = (const float*)d_in[6];
    float* y = (float*)d_out;

    ln_kernel<<<MROWS, 256>>>(x, ln_w, ln_b);

    gemm_tc<0><<<dim3(N3 / 128, MROWS / 128), 256>>>(qkv_w, qkv_b, nullptr, nullptr);

    norm_qk<<<(2 * BATCH * NH * SEQ) / 8, 256>>>();

    flash_tc<<<dim3(SEQ / 128, BATCH * NH), 256>>>();

    gemm_tc<1><<<dim3(DIM / 128, MROWS / 128), 256>>>(out_w, out_b, x, y);
}

// round 6
// speedup vs baseline: 5.8745x; 1.7383x over previous
#include <cuda_runtime.h>
#include <math.h>

#define BATCH 4
#define SEQ   2048
#define DIM   1024
#define DIMW  512            // bf16x2 words per row
#define NH    16
#define HD    64
#define MROWS (BATCH*SEQ)    // 8192
#define N3    (3*DIM)        // 3072

// ---------------- scratch (device globals; referenced ONLY in device code) --
__device__ __align__(16) unsigned g_hw[MROWS * DIMW];  // LN output, bf16x2 words
__device__ float g_q[BATCH * NH * SEQ * HD];           // fp32 [bh][t][d]
__device__ float g_k[BATCH * NH * SEQ * HD];
__device__ float g_v[BATCH * NH * SEQ * HD];
__device__ __align__(16) unsigned g_ow[MROWS * DIMW];  // attn out, bf16x2 words

// ---------------- helpers -----------------------------------------------------
// pack two fp32 -> bf16x2 word (lo = first arg, hi = second)
__device__ __forceinline__ unsigned packbf(float lo, float hi) {
    unsigned d;
    asm("cvt.rn.bf16x2.f32 %0, %1, %2;" : "=r"(d) : "f"(hi), "f"(lo));
    return d;
}

// D += A(16x16) * B(16x8), bf16 in, fp32 accum. Layout (lane = 4g+j):
//  a0=(g,2j),(g,2j+1)  a1=(g+8,2j),(g+8,2j+1)  a2=(g,2j+8),(g,2j+9)  a3=(g+8,2j+8),(g+8,2j+9)
//  b0=(k2j,g),(k2j+1,g)  b1=(k2j+8,g),(k2j+9,g)
//  c0=(g,2j) c1=(g,2j+1) c2=(g+8,2j) c3=(g+8,2j+1)
__device__ __forceinline__ void mmabf(float4& d, unsigned a0, unsigned a1,
                                      unsigned a2, unsigned a3,
                                      unsigned b0, unsigned b1) {
    asm volatile(
        "mma.sync.aligned.m16n8k16.row.col.f32.bf16.bf16.f32 "
        "{%0,%1,%2,%3}, {%4,%5,%6,%7}, {%8,%9}, {%0,%1,%2,%3};\n"
        : "+f"(d.x), "+f"(d.y), "+f"(d.z), "+f"(d.w)
        : "r"(a0), "r"(a1), "r"(a2), "r"(a3), "r"(b0), "r"(b1));
}

// ---------------- LayerNorm (fp32 math, bf16 output) ------------------------
__global__ __launch_bounds__(256) void ln_kernel(const float* __restrict__ x,
                                                 const float* __restrict__ w,
                                                 const float* __restrict__ b) {
    int row = blockIdx.x;
    const float4 v = ((const float4*)(x + (size_t)row * DIM))[threadIdx.x];
    float s  = v.x + v.y + v.z + v.w;
    float ss = v.x*v.x + v.y*v.y + v.z*v.z + v.w*v.w;

    __shared__ float sh_s[8], sh_ss[8];
    #pragma unroll
    for (int o = 16; o > 0; o >>= 1) {
        s  += __shfl_xor_sync(0xffffffffu, s,  o);
        ss += __shfl_xor_sync(0xffffffffu, ss, o);
    }
    int wid = threadIdx.x >> 5, lid = threadIdx.x & 31;
    if (lid == 0) { sh_s[wid] = s; sh_ss[wid] = ss; }
    __syncthreads();
    if (wid == 0) {
        s  = (lid < 8) ? sh_s[lid]  : 0.0f;
        ss = (lid < 8) ? sh_ss[lid] : 0.0f;
        #pragma unroll
        for (int o = 4; o > 0; o >>= 1) {
            s  += __shfl_xor_sync(0xffffffffu, s,  o);
            ss += __shfl_xor_sync(0xffffffffu, ss, o);
        }
        if (lid == 0) { sh_s[0] = s; sh_ss[0] = ss; }
    }
    __syncthreads();
    float mean = sh_s[0] * (1.0f / DIM);
    float var  = sh_ss[0] * (1.0f / DIM) - mean * mean;
    float rstd = rsqrtf(var + 1e-5f);

    const float4 wv = ((const float4*)w)[threadIdx.x];
    const float4 bv = ((const float4*)b)[threadIdx.x];
    float h0 = (v.x - mean) * rstd * wv.x + bv.x;
    float h1 = (v.y - mean) * rstd * wv.y + bv.y;
    float h2 = (v.z - mean) * rstd * wv.z + bv.z;
    float h3 = (v.w - mean) * rstd * wv.w + bv.w;
    uint2 out;
    out.x = packbf(h0, h1);
    out.y = packbf(h2, h3);
    *(uint2*)&g_hw[(size_t)row * DIMW + threadIdx.x * 2] = out;
}

// ---------------- bf16 tensor-core GEMM: C = A @ W^T (+epilogue) ------------
// 128x128 block tile, 8 warps (4m x 2n), warp tile 32x64, k-tile 32 (2 chunks).
__device__ __forceinline__ void scatter_qkv(int m, int n, float val) {
    int which = n >> 10;
    int hn = n & 1023;
    int head = hn >> 6, d = hn & 63;
    float* dst = (which == 0) ? g_q : (which == 1) ? g_k : g_v;
    int bb = m >> 11, t = m & 2047;
    dst[(((size_t)(bb * NH + head)) * SEQ + t) * HD + d] = val;
}

template<int MODE>
__global__ __launch_bounds__(256) void gemm_bf(const float* __restrict__ W,
                                               const float* __restrict__ bias,
                                               const float* __restrict__ x,
                                               float* __restrict__ y) {
    const unsigned* Asrc = (MODE == 0) ? g_hw : g_ow;  // device-side symbols
    __shared__ unsigned Aw[128 * 20];   // [row][16 words + pad4]
    __shared__ unsigned Bw[128 * 20];
    const int tid = threadIdx.x;
    const int w = tid >> 5, lane = tid & 31;
    const int g = lane >> 2, j = lane & 3;
    const int wm = w & 3, wn = w >> 2;
    const int m0 = blockIdx.y * 128;
    const int n0 = blockIdx.x * 128;

    float4 c[2][8];
    #pragma unroll
    for (int mt = 0; mt < 2; mt++)
        #pragma unroll
        for (int nt = 0; nt < 8; nt++) c[mt][nt] = make_float4(0.f, 0.f, 0.f, 0.f);

    // prefetch tile 0
    uint4  pa[2];
    float4 pb[4];
    #pragma unroll
    for (int t = 0; t < 2; t++) {
        int id = tid + 256 * t; int r = id >> 2, q4 = id & 3;
        pa[t] = *(const uint4*)&Asrc[(size_t)(m0 + r) * DIMW + q4 * 4];
    }
    #pragma unroll
    for (int t = 0; t < 4; t++) {
        int id = tid + 256 * t; int n = id >> 3, f = id & 7;
        pb[t] = *(const float4*)(W + (size_t)(n0 + n) * DIM + f * 4);
    }

    for (int kt = 0; kt < 32; kt++) {
        #pragma unroll
        for (int t = 0; t < 2; t++) {
            int id = tid + 256 * t; int r = id >> 2, q4 = id & 3;
            *(uint4*)&Aw[r * 20 + q4 * 4] = pa[t];
        }
        #pragma unroll
        for (int t = 0; t < 4; t++) {
            int id = tid + 256 * t; int n = id >> 3, f = id & 7;
            uint2 wv;
            wv.x = packbf(pb[t].x, pb[t].y);
            wv.y = packbf(pb[t].z, pb[t].w);
            *(uint2*)&Bw[n * 20 + f * 2] = wv;
        }
        __syncthreads();

        if (kt + 1 < 32) {
            #pragma unroll
            for (int t = 0; t < 2; t++) {
                int id = tid + 256 * t; int r = id >> 2, q4 = id & 3;
                pa[t] = *(const uint4*)&Asrc[(size_t)(m0 + r) * DIMW + (kt + 1) * 16 + q4 * 4];
            }
            #pragma unroll
            for (int t = 0; t < 4; t++) {
                int id = tid + 256 * t; int n = id >> 3, f = id & 7;
                pb[t] = *(const float4*)(W + (size_t)(n0 + n) * DIM + (kt + 1) * 32 + f * 4);
            }
        }

        #pragma unroll
        for (int kc = 0; kc < 2; kc++) {
            unsigned a[2][4];
            #pragma unroll
            for (int mt = 0; mt < 2; mt++) {
                int row = wm * 32 + mt * 16 + g;
                a[mt][0] = Aw[row * 20 + kc * 8 + j];
                a[mt][1] = Aw[(row + 8) * 20 + kc * 8 + j];
                a[mt][2] = Aw[row * 20 + kc * 8 + j + 4];
                a[mt][3] = Aw[(row + 8) * 20 + kc * 8 + j + 4];
            }
            unsigned b0[8], b1[8];
            #pragma unroll
            for (int nt = 0; nt < 8; nt++) {
                int n = wn * 64 + nt * 8 + g;
                b0[nt] = Bw[n * 20 + kc * 8 + j];
                b1[nt] = Bw[n * 20 + kc * 8 + j + 4];
            }
            #pragma unroll
            for (int mt = 0; mt < 2; mt++)
                #pragma unroll
                for (int nt = 0; nt < 8; nt++)
                    mmabf(c[mt][nt], a[mt][0], a[mt][1], a[mt][2], a[mt][3],
                          b0[nt], b1[nt]);
        }
        __syncthreads();
    }

    // epilogue
    #pragma unroll
    for (int mt = 0; mt < 2; mt++) {
        int r0 = m0 + wm * 32 + mt * 16 + g;
        int r1 = r0 + 8;
        #pragma unroll
        for (int nt = 0; nt < 8; nt++) {
            int n = n0 + wn * 64 + nt * 8 + 2 * j;
            float bv0 = bias[n], bv1 = bias[n + 1];
            if (MODE == 0) {
                scatter_qkv(r0, n,     c[mt][nt].x + bv0);
                scatter_qkv(r0, n + 1, c[mt][nt].y + bv1);
                scatter_qkv(r1, n,     c[mt][nt].z + bv0);
                scatter_qkv(r1, n + 1, c[mt][nt].w + bv1);
            } else {
                y[(size_t)r0 * DIM + n]     = c[mt][nt].x + bv0 + x[(size_t)r0 * DIM + n];
                y[(size_t)r0 * DIM + n + 1] = c[mt][nt].y + bv1 + x[(size_t)r0 * DIM + n + 1];
                y[(size_t)r1 * DIM + n]     = c[mt][nt].z + bv0 + x[(size_t)r1 * DIM + n];
                y[(size_t)r1 * DIM + n + 1] = c[mt][nt].w + bv1 + x[(size_t)r1 * DIM + n + 1];
            }
        }
    }
}

// ---------------- per-head L2 normalize of q (×sqrt(hd)) and k --------------
__global__ __launch_bounds__(256) void norm_qk() {
    const int R = BATCH * NH * SEQ;
    int w = (blockIdx.x * blockDim.x + threadIdx.x) >> 5;
    int lane = threadIdx.x & 31;
    float* base = (w < R) ? g_q : g_k;
    float scale = (w < R) ? 8.0f : 1.0f;   // sqrt(HD)=8 folded into q
    int row = (w < R) ? w : (w - R);
    float2 v = ((float2*)(base + (size_t)row * HD))[lane];
    float ss = v.x * v.x + v.y * v.y;
    #pragma unroll
    for (int o = 16; o > 0; o >>= 1) ss += __shfl_xor_sync(0xffffffffu, ss, o);
    float rn = scale / fmaxf(sqrtf(ss), 1e-12f);
    v.x *= rn; v.y *= rn;
    ((float2*)(base + (size_t)row * HD))[lane] = v;
}

// ---------------- flash attention, bf16 tensor-core --------------------------
// 128-row Q tile, 64-key K tile, 8 warps; warp w owns Q rows [w*16, w*16+16).
// Ksw[key n][dim-pair word], stride 36 words (conflict-free fragment reads).
// Vsp[key-pair][dim word] = bf16x2(V[2p][d], V[2p+1][d]), stride 72 words.
// P never touches smem: S C-fragments pack directly into PV A-fragments.
__global__ __launch_bounds__(256) void flash_bf() {
    __shared__ unsigned Ksw[64 * 36];   // 9.2 KB
    __shared__ unsigned Vsp[32 * 72];   // 9.2 KB

    const int tid = threadIdx.x, w = tid >> 5, lane = tid & 31;
    const int g = lane >> 2, j = lane & 3;
    const int bh = blockIdx.y;
    const int q0 = blockIdx.x * 128;

    const float* qbase = g_q + ((size_t)bh * SEQ + q0) * HD;
    const float* kbase = g_k + (size_t)bh * SEQ * HD;
    const float* vbase = g_v + (size_t)bh * SEQ * HD;

    // persistent Q A-fragments (bf16x2), 4 k-chunks of 16 dims
    unsigned qa[4][4];
    {
        const float* qr  = qbase + (size_t)(w * 16 + g) * HD;
        const float* qr8 = qr + 8 * HD;
        #pragma unroll
        for (int kc = 0; kc < 4; kc++) {
            float2 u0 = *(const float2*)(qr  + kc * 16 + 2 * j);
            float2 u1 = *(const float2*)(qr8 + kc * 16 + 2 * j);
            float2 u2 = *(const float2*)(qr  + kc * 16 + 2 * j + 8);
            float2 u3 = *(const float2*)(qr8 + kc * 16 + 2 * j + 8);
            qa[kc][0] = packbf(u0.x, u0.y);
            qa[kc][1] = packbf(u1.x, u1.y);
            qa[kc][2] = packbf(u2.x, u2.y);
            qa[kc][3] = packbf(u3.x, u3.y);
        }
    }

    float4 o[8];
    #pragma unroll
    for (int nt = 0; nt < 8; nt++) o[nt] = make_float4(0.f, 0.f, 0.f, 0.f);
    float m0r = -1e30f, m1r = -1e30f, l0 = 0.f, l1 = 0.f;

    const bool evenKey = (tid & 16) == 0;

    for (int kt = 0; kt < SEQ; kt += 64) {
        // stage K (row-major bf16x2 words) and V (key-paired words, via shfl)
        #pragma unroll
        for (int t = 0; t < 4; t++) {
            int id = tid + 256 * t;
            int n = id >> 4, d4 = id & 15;
            float4 kv = *(const float4*)(kbase + (size_t)(kt + n) * HD + d4 * 4);
            uint2 kw;
            kw.x = packbf(kv.x, kv.y);
            kw.y = packbf(kv.z, kv.w);
            *(uint2*)&Ksw[n * 36 + d4 * 2] = kw;

            float4 vv = *(const float4*)(vbase + (size_t)(kt + n) * HD + d4 * 4);
            float4 pv;
            pv.x = __shfl_xor_sync(0xffffffffu, vv.x, 16);
            pv.y = __shfl_xor_sync(0xffffffffu, vv.y, 16);
            pv.z = __shfl_xor_sync(0xffffffffu, vv.z, 16);
            pv.w = __shfl_xor_sync(0xffffffffu, vv.w, 16);
            uint2 vw; int col;
            if (evenKey) {                       // this lane holds key 2p
                vw.x = packbf(vv.x, pv.x);
                vw.y = packbf(vv.y, pv.y);
                col = d4 * 4;
            } else {                             // this lane holds key 2p+1
                vw.x = packbf(pv.z, vv.z);
                vw.y = packbf(pv.w, vv.w);
                col = d4 * 4 + 2;
            }
            *(uint2*)&Vsp[(n >> 1) * 72 + col] = vw;
        }
        __syncthreads();

        // S = Q @ K^T   (per warp: 16 x 64, 32 bf16 mmas)
        float4 c[8];
        #pragma unroll
        for (int nt = 0; nt < 8; nt++) c[nt] = make_float4(0.f, 0.f, 0.f, 0.f);
        #pragma unroll
        for (int nt = 0; nt < 8; nt++) {
            int kb = (nt * 8 + g) * 36;
            #pragma unroll
            for (int kc = 0; kc < 4; kc++) {
                unsigned b0 = Ksw[kb + kc * 8 + j];
                unsigned b1 = Ksw[kb + kc * 8 + j + 4];
                mmabf(c[nt], qa[kc][0], qa[kc][1], qa[kc][2], qa[kc][3], b0, b1);
            }
        }

        // online softmax: rows g in .x/.y, g+8 in .z/.w
        float rm0 = -1e30f, rm1 = -1e30f;
        #pragma unroll
        for (int nt = 0; nt < 8; nt++) {
            rm0 = fmaxf(rm0, fmaxf(c[nt].x, c[nt].y));
            rm1 = fmaxf(rm1, fmaxf(c[nt].z, c[nt].w));
        }
        #pragma unroll
        for (int off = 1; off <= 2; off <<= 1) {
            rm0 = fmaxf(rm0, __shfl_xor_sync(0xffffffffu, rm0, off));
            rm1 = fmaxf(rm1, __shfl_xor_sync(0xffffffffu, rm1, off));
        }
        float nm0 = fmaxf(m0r, rm0), nm1 = fmaxf(m1r, rm1);
        float al0 = __expf(m0r - nm0), al1 = __expf(m1r - nm1);
        float rs0 = 0.f, rs1 = 0.f;
        #pragma unroll
        for (int nt = 0; nt < 8; nt++) {
            c[nt].x = __expf(c[nt].x - nm0);
            c[nt].y = __expf(c[nt].y - nm0);
            c[nt].z = __expf(c[nt].z - nm1);
            c[nt].w = __expf(c[nt].w - nm1);
            rs0 += c[nt].x + c[nt].y;
            rs1 += c[nt].z + c[nt].w;
        }
        #pragma unroll
        for (int off = 1; off <= 2; off <<= 1) {
            rs0 += __shfl_xor_sync(0xffffffffu, rs0, off);
            rs1 += __shfl_xor_sync(0xffffffffu, rs1, off);
        }
        l0 = l0 * al0 + rs0;
        l1 = l1 * al1 + rs1;
        m0r = nm0; m1r = nm1;
        #pragma unroll
        for (int nt = 0; nt < 8; nt++) {
            o[nt].x *= al0; o[nt].y *= al0;
            o[nt].z *= al1; o[nt].w *= al1;
        }

        // O += P @ V : P C-frags pack directly into A-frags (no smem!)
        #pragma unroll
        for (int kc = 0; kc < 4; kc++) {
            unsigned a0 = packbf(c[2*kc].x,     c[2*kc].y);
            unsigned a1 = packbf(c[2*kc].z,     c[2*kc].w);
            unsigned a2 = packbf(c[2*kc+1].x,   c[2*kc+1].y);
            unsigned a3 = packbf(c[2*kc+1].z,   c[2*kc+1].w);
            int vb0 = (kc * 8 + j) * 72;
            int vb1 = (kc * 8 + j + 4) * 72;
            #pragma unroll
            for (int nt = 0; nt < 8; nt++) {
                unsigned b0 = Vsp[vb0 + nt * 8 + g];
                unsigned b1 = Vsp[vb1 + nt * 8 + g];
                mmabf(o[nt], a0, a1, a2, a3, b0, b1);
            }
        }
        __syncthreads();
    }

    // epilogue: rescale by 1/l, write bf16 words to g_ow [B, N, H*HD]
    float inv0 = 1.0f / l0, inv1 = 1.0f / l1;
    const int b = bh >> 4, head = bh & 15;
    size_t row0 = ((size_t)(b * SEQ + q0 + w * 16 + g)) * DIMW + head * 32;
    size_t row1 = row0 + (size_t)8 * DIMW;
    #pragma unroll
    for (int nt = 0; nt < 8; nt++) {
        g_ow[row0 + nt * 4 + j] = packbf(o[nt].x * inv0, o[nt].y * inv0);
        g_ow[row1 + nt * 4 + j] = packbf(o[nt].z * inv1, o[nt].w * inv1);
    }
}

// ---------------- launch -----------------------------------------------------
extern "C" void kernel_launch(void* const* d_in, const int* in_sizes, int n_in,
                              void* d_out, int out_size) {
    const float* x     = (const float*)d_in[0];
    const float* ln_w  = (const float*)d_in[1];
    const float* ln_b  = (const float*)d_in[2];
    const float* qkv_w = (const float*)d_in[3];
    const float* qkv_b = (const float*)d_in[4];
    const float* out_w = (const float*)d_in[5];
    const float* out_b = (const float*)d_in[6];
    float* y = (float*)d_out;

    ln_kernel<<<MROWS, 256>>>(x, ln_w, ln_b);

    gemm_bf<0><<<dim3(N3 / 128, MROWS / 128), 256>>>(qkv_w, qkv_b, nullptr, nullptr);

    norm_qk<<<(2 * BATCH * NH * SEQ) / 8, 256>>>();

    flash_bf<<<dim3(SEQ / 128, BATCH * NH), 256>>>();

    gemm_bf<1><<<dim3(DIM / 128, MROWS / 128), 256>>>(out_w, out_b, x, y);
}

// round 8
// speedup vs baseline: 6.1007x; 1.0385x over previous
#include <cuda_runtime.h>
#include <math.h>
#include <stdint.h>

#define BATCH 4
#define SEQ   2048
#define DIM   1024
#define DIMW  512            // bf16x2 words per row
#define NH    16
#define HD    64
#define MROWS (BATCH*SEQ)    // 8192
#define N3    (3*DIM)        // 3072

// ---------------- scratch (device globals; referenced ONLY in device code) --
__device__ __align__(16) unsigned g_hw[MROWS * DIMW];        // LN out, bf16x2
__device__ __align__(16) unsigned g_wq[(size_t)N3 * DIMW];   // qkv_w bf16
__device__ __align__(16) unsigned g_wo[(size_t)DIM * DIMW];  // out_w bf16
__device__ float g_q[BATCH * NH * SEQ * HD];                 // fp32 [bh][t][d]
__device__ float g_k[BATCH * NH * SEQ * HD];
__device__ float g_v[BATCH * NH * SEQ * HD];
__device__ __align__(16) unsigned g_ow[MROWS * DIMW];        // attn out, bf16x2

// ---------------- helpers -----------------------------------------------------
__device__ __forceinline__ unsigned packbf(float lo, float hi) {
    unsigned d;
    asm("cvt.rn.bf16x2.f32 %0, %1, %2;" : "=r"(d) : "f"(hi), "f"(lo));
    return d;
}
__device__ __forceinline__ float ex2(float x) {
    float r;
    asm("ex2.approx.f32 %0, %1;" : "=f"(r) : "f"(x));
    return r;
}
__device__ __forceinline__ void mmabf(float4& d, unsigned a0, unsigned a1,
                                      unsigned a2, unsigned a3,
                                      unsigned b0, unsigned b1) {
    asm volatile(
        "mma.sync.aligned.m16n8k16.row.col.f32.bf16.bf16.f32 "
        "{%0,%1,%2,%3}, {%4,%5,%6,%7}, {%8,%9}, {%0,%1,%2,%3};\n"
        : "+f"(d.x), "+f"(d.y), "+f"(d.z), "+f"(d.w)
        : "r"(a0), "r"(a1), "r"(a2), "r"(a3), "r"(b0), "r"(b1));
}

// ---------------- weight fp32 -> bf16 conversion (once per call) -------------
__global__ __launch_bounds__(256) void wconv(const float* __restrict__ qkvw,
                                             const float* __restrict__ outw) {
    size_t i = (size_t)blockIdx.x * 256 + threadIdx.x;
    const size_t NQ = (size_t)N3 * DIMW;
    const size_t NO = (size_t)DIM * DIMW;
    if (i < NQ) {
        float2 v = *(const float2*)(qkvw + 2 * i);
        g_wq[i] = packbf(v.x, v.y);
    }
    if (i < NO) {
        float2 v = *(const float2*)(outw + 2 * i);
        g_wo[i] = packbf(v.x, v.y);
    }
}

// ---------------- LayerNorm (fp32 math, bf16 output) ------------------------
__global__ __launch_bounds__(256) void ln_kernel(const float* __restrict__ x,
                                                 const float* __restrict__ w,
                                                 const float* __restrict__ b) {
    int row = blockIdx.x;
    const float4 v = ((const float4*)(x + (size_t)row * DIM))[threadIdx.x];
    float s  = v.x + v.y + v.z + v.w;
    float ss = v.x*v.x + v.y*v.y + v.z*v.z + v.w*v.w;

    __shared__ float sh_s[8], sh_ss[8];
    #pragma unroll
    for (int o = 16; o > 0; o >>= 1) {
        s  += __shfl_xor_sync(0xffffffffu, s,  o);
        ss += __shfl_xor_sync(0xffffffffu, ss, o);
    }
    int wid = threadIdx.x >> 5, lid = threadIdx.x & 31;
    if (lid == 0) { sh_s[wid] = s; sh_ss[wid] = ss; }
    __syncthreads();
    if (wid == 0) {
        s  = (lid < 8) ? sh_s[lid]  : 0.0f;
        ss = (lid < 8) ? sh_ss[lid] : 0.0f;
        #pragma unroll
        for (int o = 4; o > 0; o >>= 1) {
            s  += __shfl_xor_sync(0xffffffffu, s,  o);
            ss += __shfl_xor_sync(0xffffffffu, ss, o);
        }
        if (lid == 0) { sh_s[0] = s; sh_ss[0] = ss; }
    }
    __syncthreads();
    float mean = sh_s[0] * (1.0f / DIM);
    float var  = sh_ss[0] * (1.0f / DIM) - mean * mean;
    float rstd = rsqrtf(var + 1e-5f);

    const float4 wv = ((const float4*)w)[threadIdx.x];
    const float4 bv = ((const float4*)b)[threadIdx.x];
    uint2 out;
    out.x = packbf((v.x - mean) * rstd * wv.x + bv.x,
                   (v.y - mean) * rstd * wv.y + bv.y);
    out.y = packbf((v.z - mean) * rstd * wv.z + bv.z,
                   (v.w - mean) * rstd * wv.w + bv.w);
    *(uint2*)&g_hw[(size_t)row * DIMW + threadIdx.x * 2] = out;
}

// ---------------- bf16 mma.sync GEMM, double-buffered ------------------------
// 128x128 tile, 8 warps (4m x 2n), warp tile 32x64, k-tile 32 bf16 (16 words).
// Both A and B are pre-converted bf16 -> uint4 global loads, 1 sync per k-tile.
__device__ __forceinline__ void scatter_qkv(int m, int n, float val) {
    int which = n >> 10;
    int hn = n & 1023;
    int head = hn >> 6, d = hn & 63;
    float* dst = (which == 0) ? g_q : (which == 1) ? g_k : g_v;
    int bb = m >> 11, t = m & 2047;
    dst[(((size_t)(bb * NH + head)) * SEQ + t) * HD + d] = val;
}

template<int MODE>
__global__ __launch_bounds__(256) void gemm_bf(const float* __restrict__ bias,
                                               const float* __restrict__ x,
                                               float* __restrict__ y) {
    const unsigned* Asrc = (MODE == 0) ? g_hw : g_ow;
    const unsigned* Bsrc = (MODE == 0) ? g_wq : g_wo;
    __shared__ unsigned Aw[2][128 * 20];   // [stage][row][16 words + pad4]
    __shared__ unsigned Bw[2][128 * 20];

    const int tid = threadIdx.x;
    const int w = tid >> 5, lane = tid & 31;
    const int g = lane >> 2, j = lane & 3;
    const int wm = w & 3, wn = w >> 2;
    const int m0 = blockIdx.y * 128;
    const int n0 = blockIdx.x * 128;

    const unsigned* ag = Asrc + (size_t)m0 * DIMW;
    const unsigned* bg = Bsrc + (size_t)n0 * DIMW;
    // per k-tile: 512 uint4 per tensor; thread handles u = tid, tid+256
    const int r0l = tid >> 2, q0l = (tid & 3) * 4;          // u = tid
    const int r1l = (tid + 256) >> 2, q1l = q0l;            // u = tid+256

    float4 c[2][8];
    #pragma unroll
    for (int mt = 0; mt < 2; mt++)
        #pragma unroll
        for (int nt = 0; nt < 8; nt++) c[mt][nt] = make_float4(0.f, 0.f, 0.f, 0.f);

    // prefetch + store k-tile 0 into stage 0
    uint4 pa0, pa1, pb0, pb1;
    pa0 = *(const uint4*)(ag + (size_t)r0l * DIMW + q0l);
    pa1 = *(const uint4*)(ag + (size_t)r1l * DIMW + q1l);
    pb0 = *(const uint4*)(bg + (size_t)r0l * DIMW + q0l);
    pb1 = *(const uint4*)(bg + (size_t)r1l * DIMW + q1l);
    *(uint4*)&Aw[0][r0l * 20 + q0l] = pa0;
    *(uint4*)&Aw[0][r1l * 20 + q1l] = pa1;
    *(uint4*)&Bw[0][r0l * 20 + q0l] = pb0;
    *(uint4*)&Bw[0][r1l * 20 + q1l] = pb1;
    __syncthreads();

    for (int kt = 0; kt < 32; kt++) {
        const int cur = kt & 1, nxt = cur ^ 1;
        if (kt + 1 < 32) {
            int ko = (kt + 1) * 16;
            pa0 = *(const uint4*)(ag + (size_t)r0l * DIMW + ko + q0l);
            pa1 = *(const uint4*)(ag + (size_t)r1l * DIMW + ko + q1l);
            pb0 = *(const uint4*)(bg + (size_t)r0l * DIMW + ko + q0l);
            pb1 = *(const uint4*)(bg + (size_t)r1l * DIMW + ko + q1l);
        }

        #pragma unroll
        for (int kc = 0; kc < 2; kc++) {
            unsigned a[2][4];
            #pragma unroll
            for (int mt = 0; mt < 2; mt++) {
                int row = wm * 32 + mt * 16 + g;
                a[mt][0] = Aw[cur][row * 20 + kc * 8 + j];
                a[mt][1] = Aw[cur][(row + 8) * 20 + kc * 8 + j];
                a[mt][2] = Aw[cur][row * 20 + kc * 8 + j + 4];
                a[mt][3] = Aw[cur][(row + 8) * 20 + kc * 8 + j + 4];
            }
            unsigned b0[8], b1[8];
            #pragma unroll
            for (int nt = 0; nt < 8; nt++) {
                int n = wn * 64 + nt * 8 + g;
                b0[nt] = Bw[cur][n * 20 + kc * 8 + j];
                b1[nt] = Bw[cur][n * 20 + kc * 8 + j + 4];
            }
            #pragma unroll
            for (int mt = 0; mt < 2; mt++)
                #pragma unroll
                for (int nt = 0; nt < 8; nt++)
                    mmabf(c[mt][nt], a[mt][0], a[mt][1], a[mt][2], a[mt][3],
                          b0[nt], b1[nt]);
        }

        if (kt + 1 < 32) {
            *(uint4*)&Aw[nxt][r0l * 20 + q0l] = pa0;
            *(uint4*)&Aw[nxt][r1l * 20 + q1l] = pa1;
            *(uint4*)&Bw[nxt][r0l * 20 + q0l] = pb0;
            *(uint4*)&Bw[nxt][r1l * 20 + q1l] = pb1;
        }
        __syncthreads();
    }

    // epilogue
    #pragma unroll
    for (int mt = 0; mt < 2; mt++) {
        int r0 = m0 + wm * 32 + mt * 16 + g;
        int r1 = r0 + 8;
        #pragma unroll
        for (int nt = 0; nt < 8; nt++) {
            int n = n0 + wn * 64 + nt * 8 + 2 * j;
            float bv0 = bias[n], bv1 = bias[n + 1];
            if (MODE == 0) {
                scatter_qkv(r0, n,     c[mt][nt].x + bv0);
                scatter_qkv(r0, n + 1, c[mt][nt].y + bv1);
                scatter_qkv(r1, n,     c[mt][nt].z + bv0);
                scatter_qkv(r1, n + 1, c[mt][nt].w + bv1);
            } else {
                y[(size_t)r0 * DIM + n]     = c[mt][nt].x + bv0 + x[(size_t)r0 * DIM + n];
                y[(size_t)r0 * DIM + n + 1] = c[mt][nt].y + bv1 + x[(size_t)r0 * DIM + n + 1];
                y[(size_t)r1 * DIM + n]     = c[mt][nt].z + bv0 + x[(size_t)r1 * DIM + n];
                y[(size_t)r1 * DIM + n + 1] = c[mt][nt].w + bv1 + x[(size_t)r1 * DIM + n + 1];
            }
        }
    }
}

// ---------------- per-head L2 normalize; q gets sqrt(hd)*log2(e) folded -----
__global__ __launch_bounds__(256) void norm_qk() {
    const int R = BATCH * NH * SEQ;
    int w = (blockIdx.x * blockDim.x + threadIdx.x) >> 5;
    int lane = threadIdx.x & 31;
    float* base = (w < R) ? g_q : g_k;
    // q: 8 (sqrt(HD)) * log2(e), so softmax runs in exp2 domain
    float scale = (w < R) ? 8.0f * 1.4426950408889634f : 1.0f;
    int row = (w < R) ? w : (w - R);
    float2 v = ((float2*)(base + (size_t)row * HD))[lane];
    float ss = v.x * v.x + v.y * v.y;
    #pragma unroll
    for (int o = 16; o > 0; o >>= 1) ss += __shfl_xor_sync(0xffffffffu, ss, o);
    float rn = scale / fmaxf(sqrtf(ss), 1e-12f);
    v.x *= rn; v.y *= rn;
    ((float2*)(base + (size_t)row * HD))[lane] = v;
}

// ---------------- flash attention, bf16 mma.sync ------------------------------
__global__ __launch_bounds__(256) void flash_bf() {
    __shared__ unsigned Ksw[64 * 36];
    __shared__ unsigned Vsp[32 * 72];

    const int tid = threadIdx.x, w = tid >> 5, lane = tid & 31;
    const int g = lane >> 2, j = lane & 3;
    const int bh = blockIdx.y;
    const int q0 = blockIdx.x * 128;

    const float* qbase = g_q + ((size_t)bh * SEQ + q0) * HD;
    const float* kbase = g_k + (size_t)bh * SEQ * HD;
    const float* vbase = g_v + (size_t)bh * SEQ * HD;

    unsigned qa[4][4];
    {
        const float* qr  = qbase + (size_t)(w * 16 + g) * HD;
        const float* qr8 = qr + 8 * HD;
        #pragma unroll
        for (int kc = 0; kc < 4; kc++) {
            float2 u0 = *(const float2*)(qr  + kc * 16 + 2 * j);
            float2 u1 = *(const float2*)(qr8 + kc * 16 + 2 * j);
            float2 u2 = *(const float2*)(qr  + kc * 16 + 2 * j + 8);
            float2 u3 = *(const float2*)(qr8 + kc * 16 + 2 * j + 8);
            qa[kc][0] = packbf(u0.x, u0.y);
            qa[kc][1] = packbf(u1.x, u1.y);
            qa[kc][2] = packbf(u2.x, u2.y);
            qa[kc][3] = packbf(u3.x, u3.y);
        }
    }

    float4 o[8];
    #pragma unroll
    for (int nt = 0; nt < 8; nt++) o[nt] = make_float4(0.f, 0.f, 0.f, 0.f);
    float m0r = -1e30f, m1r = -1e30f, l0 = 0.f, l1 = 0.f;

    const bool evenKey = (tid & 16) == 0;

    for (int kt = 0; kt < SEQ; kt += 64) {
        #pragma unroll
        for (int t = 0; t < 4; t++) {
            int id = tid + 256 * t;
            int n = id >> 4, d4 = id & 15;
            float4 kv = *(const float4*)(kbase + (size_t)(kt + n) * HD + d4 * 4);
            uint2 kw;
            kw.x = packbf(kv.x, kv.y);
            kw.y = packbf(kv.z, kv.w);
            *(uint2*)&Ksw[n * 36 + d4 * 2] = kw;

            float4 vv = *(const float4*)(vbase + (size_t)(kt + n) * HD + d4 * 4);
            float4 pv;
            pv.x = __shfl_xor_sync(0xffffffffu, vv.x, 16);
            pv.y = __shfl_xor_sync(0xffffffffu, vv.y, 16);
            pv.z = __shfl_xor_sync(0xffffffffu, vv.z, 16);
            pv.w = __shfl_xor_sync(0xffffffffu, vv.w, 16);
            uint2 vw; int col;
            if (evenKey) {
                vw.x = packbf(vv.x, pv.x);
                vw.y = packbf(vv.y, pv.y);
                col = d4 * 4;
            } else {
                vw.x = packbf(pv.z, vv.z);
                vw.y = packbf(pv.w, vv.w);
                col = d4 * 4 + 2;
            }
            *(uint2*)&Vsp[(n >> 1) * 72 + col] = vw;
        }
        __syncthreads();

        float4 c[8];
        #pragma unroll
        for (int nt = 0; nt < 8; nt++) c[nt] = make_float4(0.f, 0.f, 0.f, 0.f);
        #pragma unroll
        for (int nt = 0; nt < 8; nt++) {
            int kb = (nt * 8 + g) * 36;
            #pragma unroll
            for (int kc = 0; kc < 4; kc++) {
                unsigned b0 = Ksw[kb + kc * 8 + j];
                unsigned b1 = Ksw[kb + kc * 8 + j + 4];
                mmabf(c[nt], qa[kc][0], qa[kc][1], qa[kc][2], qa[kc][3], b0, b1);
            }
        }

        // online softmax in exp2 domain (log2e pre-folded into q)
        float rm0 = -1e30f, rm1 = -1e30f;
        #pragma unroll
        for (int nt = 0; nt < 8; nt++) {
            rm0 = fmaxf(rm0, fmaxf(c[nt].x, c[nt].y));
            rm1 = fmaxf(rm1, fmaxf(c[nt].z, c[nt].w));
        }
        #pragma unroll
        for (int off = 1; off <= 2; off <<= 1) {
            rm0 = fmaxf(rm0, __shfl_xor_sync(0xffffffffu, rm0, off));
            rm1 = fmaxf(rm1, __shfl_xor_sync(0xffffffffu, rm1, off));
        }
        float nm0 = fmaxf(m0r, rm0), nm1 = fmaxf(m1r, rm1);
        float al0 = ex2(m0r - nm0), al1 = ex2(m1r - nm1);
        float rs0 = 0.f, rs1 = 0.f;
        #pragma unroll
        for (int nt = 0; nt < 8; nt++) {
            c[nt].x = ex2(c[nt].x - nm0);
            c[nt].y = ex2(c[nt].y - nm0);
            c[nt].z = ex2(c[nt].z - nm1);
            c[nt].w = ex2(c[nt].w - nm1);
            rs0 += c[nt].x + c[nt].y;
            rs1 += c[nt].z + c[nt].w;
        }
        #pragma unroll
        for (int off = 1; off <= 2; off <<= 1) {
            rs0 += __shfl_xor_sync(0xffffffffu, rs0, off);
            rs1 += __shfl_xor_sync(0xffffffffu, rs1, off);
        }
        l0 = l0 * al0 + rs0;
        l1 = l1 * al1 + rs1;
        m0r = nm0; m1r = nm1;
        #pragma unroll
        for (int nt = 0; nt < 8; nt++) {
            o[nt].x *= al0; o[nt].y *= al0;
            o[nt].z *= al1; o[nt].w *= al1;
        }

        #pragma unroll
        for (int kc = 0; kc < 4; kc++) {
            unsigned a0 = packbf(c[2*kc].x,   c[2*kc].y);
            unsigned a1 = packbf(c[2*kc].z,   c[2*kc].w);
            unsigned a2 = packbf(c[2*kc+1].x, c[2*kc+1].y);
            unsigned a3 = packbf(c[2*kc+1].z, c[2*kc+1].w);
            int vb0 = (kc * 8 + j) * 72;
            int vb1 = (kc * 8 + j + 4) * 72;
            #pragma unroll
            for (int nt = 0; nt < 8; nt++) {
                unsigned b0 = Vsp[vb0 + nt * 8 + g];
                unsigned b1 = Vsp[vb1 + nt * 8 + g];
                mmabf(o[nt], a0, a1, a2, a3, b0, b1);
            }
        }
        __syncthreads();
    }

    float inv0 = 1.0f / l0, inv1 = 1.0f / l1;
    const int b = bh >> 4, head = bh & 15;
    size_t row0 = ((size_t)(b * SEQ + q0 + w * 16 + g)) * DIMW + head * 32;
    size_t row1 = row0 + (size_t)8 * DIMW;
    #pragma unroll
    for (int nt = 0; nt < 8; nt++) {
        g_ow[row0 + nt * 4 + j] = packbf(o[nt].x * inv0, o[nt].y * inv0);
        g_ow[row1 + nt * 4 + j] = packbf(o[nt].z * inv1, o[nt].w * inv1);
    }
}

// ---------------- launch -----------------------------------------------------
extern "C" void kernel_launch(void* const* d_in, const int* in_sizes, int n_in,
                              void* d_out, int out_size) {
    const float* x     = (const float*)d_in[0];
    const float* ln_w  = (const float*)d_in[1];
    const float* ln_b  = (const float*)d_in[2];
    const float* qkv_w = (const float*)d_in[3];
    const float* qkv_b = (const float*)d_in[4];
    const float* out_w = (const float*)d_in[5];
    const float* out_b = (const float*)d_in[6];
    float* y = (float*)d_out;

    wconv<<<(N3 * DIMW) / 256, 256>>>(qkv_w, out_w);

    ln_kernel<<<MROWS, 256>>>(x, ln_w, ln_b);

    gemm_bf<0><<<dim3(N3 / 128, MROWS / 128), 256>>>(qkv_b, nullptr, nullptr);

    norm_qk<<<(2 * BATCH * NH * SEQ) / 8, 256>>>();

    flash_bf<<<dim3(SEQ / 128, BATCH * NH), 256>>>();

    gemm_bf<1><<<dim3(DIM / 128, MROWS / 128), 256>>>(out_b, x, y);
}

// round 9
// speedup vs baseline: 6.8694x; 1.1260x over previous
#include <cuda_runtime.h>
#include <math.h>
#include <stdint.h>

#define BATCH 4
#define SEQ   2048
#define DIM   1024
#define DIMW  512            // bf16x2 words per row
#define NH    16
#define HD    64
#define HDW   32             // bf16x2 words per head row
#define MROWS (BATCH*SEQ)    // 8192
#define N3    (3*DIM)        // 3072
#define NROWS (BATCH*NH*SEQ) // 131072 head rows

// logit bound in exp2 domain: 8*log2(e) = 11.5416
#define FIXED_MAX 11.6f

// ---------------- scratch (device globals; referenced ONLY in device code) --
__device__ __align__(16) unsigned g_hw[MROWS * DIMW];        // LN out, bf16x2
__device__ __align__(16) unsigned g_wq[(size_t)N3 * DIMW];   // qkv_w bf16
__device__ __align__(16) unsigned g_wo[(size_t)DIM * DIMW];  // out_w bf16
__device__ __align__(16) unsigned g_qw[(size_t)NROWS * HDW]; // q bf16 [bh][t][dw]
__device__ __align__(16) unsigned g_kw[(size_t)NROWS * HDW];
__device__ __align__(16) unsigned g_vw[(size_t)NROWS * HDW];
__device__ __align__(16) unsigned g_ow[MROWS * DIMW];        // attn out, bf16x2

// ---------------- helpers -----------------------------------------------------
__device__ __forceinline__ unsigned packbf(float lo, float hi) {
    unsigned d;
    asm("cvt.rn.bf16x2.f32 %0, %1, %2;" : "=r"(d) : "f"(hi), "f"(lo));
    return d;
}
__device__ __forceinline__ float ex2(float x) {
    float r;
    asm("ex2.approx.f32 %0, %1;" : "=f"(r) : "f"(x));
    return r;
}
__device__ __forceinline__ unsigned prmt(unsigned a, unsigned b, unsigned s) {
    unsigned d;
    asm("prmt.b32 %0, %1, %2, %3;" : "=r"(d) : "r"(a), "r"(b), "r"(s));
    return d;
}
__device__ __forceinline__ void mmabf(float4& d, unsigned a0, unsigned a1,
                                      unsigned a2, unsigned a3,
                                      unsigned b0, unsigned b1) {
    asm volatile(
        "mma.sync.aligned.m16n8k16.row.col.f32.bf16.bf16.f32 "
        "{%0,%1,%2,%3}, {%4,%5,%6,%7}, {%8,%9}, {%0,%1,%2,%3};\n"
        : "+f"(d.x), "+f"(d.y), "+f"(d.z), "+f"(d.w)
        : "r"(a0), "r"(a1), "r"(a2), "r"(a3), "r"(b0), "r"(b1));
}

// ---------------- weight fp32 -> bf16 conversion (once per call) -------------
__global__ __launch_bounds__(256) void wconv(const float* __restrict__ qkvw,
                                             const float* __restrict__ outw) {
    size_t i = (size_t)blockIdx.x * 256 + threadIdx.x;
    const size_t NQ = (size_t)N3 * DIMW;
    const size_t NO = (size_t)DIM * DIMW;
    if (i < NQ) {
        float2 v = *(const float2*)(qkvw + 2 * i);
        g_wq[i] = packbf(v.x, v.y);
    }
    if (i < NO) {
        float2 v = *(const float2*)(outw + 2 * i);
        g_wo[i] = packbf(v.x, v.y);
    }
}

// ---------------- LayerNorm (fp32 math, bf16 output) ------------------------
__global__ __launch_bounds__(256) void ln_kernel(const float* __restrict__ x,
                                                 const float* __restrict__ w,
                                                 const float* __restrict__ b) {
    int row = blockIdx.x;
    const float4 v = ((const float4*)(x + (size_t)row * DIM))[threadIdx.x];
    float s  = v.x + v.y + v.z + v.w;
    float ss = v.x*v.x + v.y*v.y + v.z*v.z + v.w*v.w;

    __shared__ float sh_s[8], sh_ss[8];
    #pragma unroll
    for (int o = 16; o > 0; o >>= 1) {
        s  += __shfl_xor_sync(0xffffffffu, s,  o);
        ss += __shfl_xor_sync(0xffffffffu, ss, o);
    }
    int wid = threadIdx.x >> 5, lid = threadIdx.x & 31;
    if (lid == 0) { sh_s[wid] = s; sh_ss[wid] = ss; }
    __syncthreads();
    if (wid == 0) {
        s  = (lid < 8) ? sh_s[lid]  : 0.0f;
        ss = (lid < 8) ? sh_ss[lid] : 0.0f;
        #pragma unroll
        for (int o = 4; o > 0; o >>= 1) {
            s  += __shfl_xor_sync(0xffffffffu, s,  o);
            ss += __shfl_xor_sync(0xffffffffu, ss, o);
        }
        if (lid == 0) { sh_s[0] = s; sh_ss[0] = ss; }
    }
    __syncthreads();
    float mean = sh_s[0] * (1.0f / DIM);
    float var  = sh_ss[0] * (1.0f / DIM) - mean * mean;
    float rstd = rsqrtf(var + 1e-5f);

    const float4 wv = ((const float4*)w)[threadIdx.x];
    const float4 bv = ((const float4*)b)[threadIdx.x];
    uint2 out;
    out.x = packbf((v.x - mean) * rstd * wv.x + bv.x,
                   (v.y - mean) * rstd * wv.y + bv.y);
    out.y = packbf((v.z - mean) * rstd * wv.z + bv.z,
                   (v.w - mean) * rstd * wv.w + bv.w);
    *(uint2*)&g_hw[(size_t)row * DIMW + threadIdx.x * 2] = out;
}

// ---------------- bf16 mma.sync GEMM, double-buffered ------------------------
// MODE 0: A=g_hw, B=g_wq, scatter bf16 words into q/k/v (+bias).
// MODE 1: A=g_ow, B=g_wo, y = C + bias + x (fp32).
__device__ __forceinline__ void scatter2(int m, int n, float v0, float v1) {
    int which = n >> 10;
    int hn = n & 1023;
    int head = hn >> 6, d = hn & 63;
    unsigned* dst = (which == 0) ? g_qw : (which == 1) ? g_kw : g_vw;
    int bb = m >> 11, t = m & 2047;
    dst[(((size_t)(bb * NH + head)) * SEQ + t) * HDW + (d >> 1)] = packbf(v0, v1);
}

template<int MODE>
__global__ __launch_bounds__(256) void gemm_bf(const float* __restrict__ bias,
                                               const float* __restrict__ x,
                                               float* __restrict__ y) {
    const unsigned* Asrc = (MODE == 0) ? g_hw : g_ow;
    const unsigned* Bsrc = (MODE == 0) ? g_wq : g_wo;
    __shared__ unsigned Aw[2][128 * 20];
    __shared__ unsigned Bw[2][128 * 20];

    const int tid = threadIdx.x;
    const int w = tid >> 5, lane = tid & 31;
    const int g = lane >> 2, j = lane & 3;
    const int wm = w & 3, wn = w >> 2;
    const int m0 = blockIdx.y * 128;
    const int n0 = blockIdx.x * 128;

    const unsigned* ag = Asrc + (size_t)m0 * DIMW;
    const unsigned* bg = Bsrc + (size_t)n0 * DIMW;
    const int r0l = tid >> 2, q0l = (tid & 3) * 4;
    const int r1l = (tid + 256) >> 2, q1l = q0l;

    float4 c[2][8];
    #pragma unroll
    for (int mt = 0; mt < 2; mt++)
        #pragma unroll
        for (int nt = 0; nt < 8; nt++) c[mt][nt] = make_float4(0.f, 0.f, 0.f, 0.f);

    uint4 pa0, pa1, pb0, pb1;
    pa0 = *(const uint4*)(ag + (size_t)r0l * DIMW + q0l);
    pa1 = *(const uint4*)(ag + (size_t)r1l * DIMW + q1l);
    pb0 = *(const uint4*)(bg + (size_t)r0l * DIMW + q0l);
    pb1 = *(const uint4*)(bg + (size_t)r1l * DIMW + q1l);
    *(uint4*)&Aw[0][r0l * 20 + q0l] = pa0;
    *(uint4*)&Aw[0][r1l * 20 + q1l] = pa1;
    *(uint4*)&Bw[0][r0l * 20 + q0l] = pb0;
    *(uint4*)&Bw[0][r1l * 20 + q1l] = pb1;
    __syncthreads();

    for (int kt = 0; kt < 32; kt++) {
        const int cur = kt & 1, nxt = cur ^ 1;
        if (kt + 1 < 32) {
            int ko = (kt + 1) * 16;
            pa0 = *(const uint4*)(ag + (size_t)r0l * DIMW + ko + q0l);
            pa1 = *(const uint4*)(ag + (size_t)r1l * DIMW + ko + q1l);
            pb0 = *(const uint4*)(bg + (size_t)r0l * DIMW + ko + q0l);
            pb1 = *(const uint4*)(bg + (size_t)r1l * DIMW + ko + q1l);
        }

        #pragma unroll
        for (int kc = 0; kc < 2; kc++) {
            unsigned a[2][4];
            #pragma unroll
            for (int mt = 0; mt < 2; mt++) {
                int row = wm * 32 + mt * 16 + g;
                a[mt][0] = Aw[cur][row * 20 + kc * 8 + j];
                a[mt][1] = Aw[cur][(row + 8) * 20 + kc * 8 + j];
                a[mt][2] = Aw[cur][row * 20 + kc * 8 + j + 4];
                a[mt][3] = Aw[cur][(row + 8) * 20 + kc * 8 + j + 4];
            }
            unsigned b0[8], b1[8];
            #pragma unroll
            for (int nt = 0; nt < 8; nt++) {
                int n = wn * 64 + nt * 8 + g;
                b0[nt] = Bw[cur][n * 20 + kc * 8 + j];
                b1[nt] = Bw[cur][n * 20 + kc * 8 + j + 4];
            }
            #pragma unroll
            for (int mt = 0; mt < 2; mt++)
                #pragma unroll
                for (int nt = 0; nt < 8; nt++)
                    mmabf(c[mt][nt], a[mt][0], a[mt][1], a[mt][2], a[mt][3],
                          b0[nt], b1[nt]);
        }

        if (kt + 1 < 32) {
            *(uint4*)&Aw[nxt][r0l * 20 + q0l] = pa0;
            *(uint4*)&Aw[nxt][r1l * 20 + q1l] = pa1;
            *(uint4*)&Bw[nxt][r0l * 20 + q0l] = pb0;
            *(uint4*)&Bw[nxt][r1l * 20 + q1l] = pb1;
        }
        __syncthreads();
    }

    #pragma unroll
    for (int mt = 0; mt < 2; mt++) {
        int r0 = m0 + wm * 32 + mt * 16 + g;
        int r1 = r0 + 8;
        #pragma unroll
        for (int nt = 0; nt < 8; nt++) {
            int n = n0 + wn * 64 + nt * 8 + 2 * j;
            float bv0 = bias[n], bv1 = bias[n + 1];
            if (MODE == 0) {
                scatter2(r0, n, c[mt][nt].x + bv0, c[mt][nt].y + bv1);
                scatter2(r1, n, c[mt][nt].z + bv0, c[mt][nt].w + bv1);
            } else {
                y[(size_t)r0 * DIM + n]     = c[mt][nt].x + bv0 + x[(size_t)r0 * DIM + n];
                y[(size_t)r0 * DIM + n + 1] = c[mt][nt].y + bv1 + x[(size_t)r0 * DIM + n + 1];
                y[(size_t)r1 * DIM + n]     = c[mt][nt].z + bv0 + x[(size_t)r1 * DIM + n];
                y[(size_t)r1 * DIM + n + 1] = c[mt][nt].w + bv1 + x[(size_t)r1 * DIM + n + 1];
            }
        }
    }
}

// ---------------- per-head L2 normalize (bf16 in place) ----------------------
// q also gets sqrt(HD)*log2(e) folded (exp2-domain softmax).
__global__ __launch_bounds__(256) void norm_qk() {
    int w = (blockIdx.x * blockDim.x + threadIdx.x) >> 5;
    int lane = threadIdx.x & 31;
    unsigned* base = (w < NROWS) ? g_qw : g_kw;
    float scale = (w < NROWS) ? 8.0f * 1.4426950408889634f : 1.0f;
    int row = (w < NROWS) ? w : (w - NROWS);
    unsigned wv = base[(size_t)row * HDW + lane];
    float lo = __uint_as_float(wv << 16);
    float hi = __uint_as_float(wv & 0xffff0000u);
    float ss = lo * lo + hi * hi;
    #pragma unroll
    for (int o = 16; o > 0; o >>= 1) ss += __shfl_xor_sync(0xffffffffu, ss, o);
    float rn = scale / fmaxf(sqrtf(ss), 1e-12f);
    base[(size_t)row * HDW + lane] = packbf(lo * rn, hi * rn);
}

// ---------------- flash attention: fixed-max softmax, bf16, double-buffered --
__global__ __launch_bounds__(256) void flash_bf() {
    __shared__ unsigned Ksw[2][64 * 36];   // [buf][key][dim-pair word]
    __shared__ unsigned Vsp[2][32 * 72];   // [buf][key-pair][dim word]

    const int tid = threadIdx.x, w = tid >> 5, lane = tid & 31;
    const int g = lane >> 2, j = lane & 3;
    const int bh = blockIdx.y;
    const int q0 = blockIdx.x * 128;

    const unsigned* qw = g_qw + ((size_t)bh * SEQ + q0) * HDW;
    const unsigned* kw = g_kw + (size_t)bh * SEQ * HDW;
    const unsigned* vw = g_vw + (size_t)bh * SEQ * HDW;

    // persistent Q fragments: direct bf16x2 word loads
    unsigned qa[4][4];
    {
        const unsigned* qr  = qw + (size_t)(w * 16 + g) * HDW;
        const unsigned* qr8 = qr + 8 * HDW;
        #pragma unroll
        for (int kc = 0; kc < 4; kc++) {
            qa[kc][0] = qr [kc * 8 + j];
            qa[kc][1] = qr8[kc * 8 + j];
            qa[kc][2] = qr [kc * 8 + j + 4];
            qa[kc][3] = qr8[kc * 8 + j + 4];
        }
    }

    // stage lambda-ish: K direct copy; V via prmt key-pair interleave
    const int kn  = tid >> 3, kq = (tid & 7) * 4;          // K task (id = tid)
    const int kn2 = (tid + 256) >> 3, kq2 = kq;            // K task (id = tid+256)
    const int vp  = tid >> 4, vc = (tid & 15) * 2;         // V task (id = tid)
    const int vp2 = (tid + 256) >> 4, vc2 = vc;            // V task (id = tid+256)

#define STAGE(buf, kt) do {                                                     \
    *(uint4*)&Ksw[buf][kn  * 36 + kq ] =                                        \
        *(const uint4*)&kw[(size_t)((kt) + kn ) * HDW + kq ];                   \
    *(uint4*)&Ksw[buf][kn2 * 36 + kq2] =                                        \
        *(const uint4*)&kw[(size_t)((kt) + kn2) * HDW + kq2];                   \
    {                                                                           \
        uint2 w0 = *(const uint2*)&vw[(size_t)((kt) + 2*vp    ) * HDW + vc ];   \
        uint2 w1 = *(const uint2*)&vw[(size_t)((kt) + 2*vp + 1) * HDW + vc ];   \
        uint4 ov;                                                               \
        ov.x = prmt(w0.x, w1.x, 0x5410u); ov.y = prmt(w0.x, w1.x, 0x7632u);     \
        ov.z = prmt(w0.y, w1.y, 0x5410u); ov.w = prmt(w0.y, w1.y, 0x7632u);     \
        *(uint4*)&Vsp[buf][vp * 72 + vc * 2] = ov;                              \
        w0 = *(const uint2*)&vw[(size_t)((kt) + 2*vp2    ) * HDW + vc2];        \
        w1 = *(const uint2*)&vw[(size_t)((kt) + 2*vp2 + 1) * HDW + vc2];        \
        ov.x = prmt(w0.x, w1.x, 0x5410u); ov.y = prmt(w0.x, w1.x, 0x7632u);     \
        ov.z = prmt(w0.y, w1.y, 0x5410u); ov.w = prmt(w0.y, w1.y, 0x7632u);     \
        *(uint4*)&Vsp[buf][vp2 * 72 + vc2 * 2] = ov;                            \
    }                                                                           \
} while (0)

    float4 o[8];
    #pragma unroll
    for (int nt = 0; nt < 8; nt++) o[nt] = make_float4(0.f, 0.f, 0.f, 0.f);
    float l0 = 0.f, l1 = 0.f;

    STAGE(0, 0);
    __syncthreads();

    for (int it = 0; it < SEQ / 64; it++) {
        const int cur = it & 1;
        if (it + 1 < SEQ / 64) STAGE(cur ^ 1, (it + 1) * 64);

        // S = Q @ K^T
        float4 c[8];
        #pragma unroll
        for (int nt = 0; nt < 8; nt++) c[nt] = make_float4(0.f, 0.f, 0.f, 0.f);
        #pragma unroll
        for (int nt = 0; nt < 8; nt++) {
            int kb = (nt * 8 + g) * 36;
            #pragma unroll
            for (int kc = 0; kc < 4; kc++) {
                unsigned b0 = Ksw[cur][kb + kc * 8 + j];
                unsigned b1 = Ksw[cur][kb + kc * 8 + j + 4];
                mmabf(c[nt], qa[kc][0], qa[kc][1], qa[kc][2], qa[kc][3], b0, b1);
            }
        }

        // fixed-max softmax: P = exp2(s - C); l accumulates per-thread
        #pragma unroll
        for (int nt = 0; nt < 8; nt++) {
            c[nt].x = ex2(c[nt].x - FIXED_MAX);
            c[nt].y = ex2(c[nt].y - FIXED_MAX);
            c[nt].z = ex2(c[nt].z - FIXED_MAX);
            c[nt].w = ex2(c[nt].w - FIXED_MAX);
            l0 += c[nt].x + c[nt].y;
            l1 += c[nt].z + c[nt].w;
        }

        // O += P @ V (P C-frags pack straight into A-frags)
        #pragma unroll
        for (int kc = 0; kc < 4; kc++) {
            unsigned a0 = packbf(c[2*kc].x,   c[2*kc].y);
            unsigned a1 = packbf(c[2*kc].z,   c[2*kc].w);
            unsigned a2 = packbf(c[2*kc+1].x, c[2*kc+1].y);
            unsigned a3 = packbf(c[2*kc+1].z, c[2*kc+1].w);
            int vb0 = (kc * 8 + j) * 72;
            int vb1 = (kc * 8 + j + 4) * 72;
            #pragma unroll
            for (int nt = 0; nt < 8; nt++) {
                unsigned b0 = Vsp[cur][vb0 + nt * 8 + g];
                unsigned b1 = Vsp[cur][vb1 + nt * 8 + g];
                mmabf(o[nt], a0, a1, a2, a3, b0, b1);
            }
        }
        __syncthreads();
    }

    // one l reduction for the whole kernel (quad lanes share a row)
    #pragma unroll
    for (int off = 1; off <= 2; off <<= 1) {
        l0 += __shfl_xor_sync(0xffffffffu, l0, off);
        l1 += __shfl_xor_sync(0xffffffffu, l1, off);
    }
    float inv0 = 1.0f / l0, inv1 = 1.0f / l1;

    const int b = bh >> 4, head = bh & 15;
    size_t row0 = ((size_t)(b * SEQ + q0 + w * 16 + g)) * DIMW + head * 32;
    size_t row1 = row0 + (size_t)8 * DIMW;
    #pragma unroll
    for (int nt = 0; nt < 8; nt++) {
        g_ow[row0 + nt * 4 + j] = packbf(o[nt].x * inv0, o[nt].y * inv0);
        g_ow[row1 + nt * 4 + j] = packbf(o[nt].z * inv1, o[nt].w * inv1);
    }
#undef STAGE
}

// ---------------- launch -----------------------------------------------------
extern "C" void kernel_launch(void* const* d_in, const int* in_sizes, int n_in,
                              void* d_out, int out_size) {
    const float* x     = (const float*)d_in[0];
    const float* ln_w  = (const float*)d_in[1];
    const float* ln_b  = (const float*)d_in[2];
    const float* qkv_w = (const float*)d_in[3];
    const float* qkv_b = (const float*)d_in[4];
    const float* out_w = (const float*)d_in[5];
    const float* out_b = (const float*)d_in[6];
    float* y = (float*)d_out;

    wconv<<<(N3 * DIMW) / 256, 256>>>(qkv_w, out_w);

    ln_kernel<<<MROWS, 256>>>(x, ln_w, ln_b);

    gemm_bf<0><<<dim3(N3 / 128, MROWS / 128), 256>>>(qkv_b, nullptr, nullptr);

    norm_qk<<<(2 * NROWS) / 8, 256>>>();

    flash_bf<<<dim3(SEQ / 128, BATCH * NH), 256>>>();

    gemm_bf<1><<<dim3(DIM / 128, MROWS / 128), 256>>>(out_b, x, y);
}

// round 10
// speedup vs baseline: 7.0566x; 1.0273x over previous
#include <cuda_runtime.h>
#include <math.h>
#include <stdint.h>

#define BATCH 4
#define SEQ   2048
#define DIM   1024
#define DIMW  512            // bf16x2 words per row
#define NH    16
#define HD    64
#define HDW   32             // bf16x2 words per head row
#define MROWS (BATCH*SEQ)    // 8192
#define N3    (3*DIM)        // 3072
#define NROWS (BATCH*NH*SEQ) // 131072 head rows

// logit bound in exp2 domain: 8*log2(e) = 11.5416
#define FIXED_MAX 11.6f
#define QSCALE (8.0f * 1.4426950408889634f)

// ---------------- scratch (device globals; referenced ONLY in device code) --
__device__ __align__(16) unsigned g_hw[MROWS * DIMW];        // LN out, bf16x2
__device__ __align__(16) unsigned g_wq[(size_t)N3 * DIMW];   // qkv_w bf16
__device__ __align__(16) unsigned g_wo[(size_t)DIM * DIMW];  // out_w bf16
__device__ __align__(16) unsigned g_qw[(size_t)NROWS * HDW]; // q bf16 [bh][t][dw]
__device__ __align__(16) unsigned g_kw[(size_t)NROWS * HDW];
__device__ __align__(16) unsigned g_vw[(size_t)NROWS * HDW];
__device__ __align__(16) unsigned g_ow[MROWS * DIMW];        // attn out, bf16x2

// ---------------- helpers -----------------------------------------------------
__device__ __forceinline__ unsigned packbf(float lo, float hi) {
    unsigned d;
    asm("cvt.rn.bf16x2.f32 %0, %1, %2;" : "=r"(d) : "f"(hi), "f"(lo));
    return d;
}
__device__ __forceinline__ float ex2(float x) {
    float r;
    asm("ex2.approx.f32 %0, %1;" : "=f"(r) : "f"(x));
    return r;
}
__device__ __forceinline__ unsigned prmt(unsigned a, unsigned b, unsigned s) {
    unsigned d;
    asm("prmt.b32 %0, %1, %2, %3;" : "=r"(d) : "r"(a), "r"(b), "r"(s));
    return d;
}
__device__ __forceinline__ void mmabf(float4& d, unsigned a0, unsigned a1,
                                      unsigned a2, unsigned a3,
                                      unsigned b0, unsigned b1) {
    asm volatile(
        "mma.sync.aligned.m16n8k16.row.col.f32.bf16.bf16.f32 "
        "{%0,%1,%2,%3}, {%4,%5,%6,%7}, {%8,%9}, {%0,%1,%2,%3};\n"
        : "+f"(d.x), "+f"(d.y), "+f"(d.z), "+f"(d.w)
        : "r"(a0), "r"(a1), "r"(a2), "r"(a3), "r"(b0), "r"(b1));
}

// ---------------- weight fp32 -> bf16 conversion (once per call) -------------
__global__ __launch_bounds__(256) void wconv(const float* __restrict__ qkvw,
                                             const float* __restrict__ outw) {
    size_t i = (size_t)blockIdx.x * 256 + threadIdx.x;
    const size_t NQ = (size_t)N3 * DIMW;
    const size_t NO = (size_t)DIM * DIMW;
    if (i < NQ) {
        float2 v = *(const float2*)(qkvw + 2 * i);
        g_wq[i] = packbf(v.x, v.y);
    }
    if (i < NO) {
        float2 v = *(const float2*)(outw + 2 * i);
        g_wo[i] = packbf(v.x, v.y);
    }
}

// ---------------- LayerNorm (fp32 math, bf16 output) ------------------------
__global__ __launch_bounds__(256) void ln_kernel(const float* __restrict__ x,
                                                 const float* __restrict__ w,
                                                 const float* __restrict__ b) {
    int row = blockIdx.x;
    const float4 v = ((const float4*)(x + (size_t)row * DIM))[threadIdx.x];
    float s  = v.x + v.y + v.z + v.w;
    float ss = v.x*v.x + v.y*v.y + v.z*v.z + v.w*v.w;

    __shared__ float sh_s[8], sh_ss[8];
    #pragma unroll
    for (int o = 16; o > 0; o >>= 1) {
        s  += __shfl_xor_sync(0xffffffffu, s,  o);
        ss += __shfl_xor_sync(0xffffffffu, ss, o);
    }
    int wid = threadIdx.x >> 5, lid = threadIdx.x & 31;
    if (lid == 0) { sh_s[wid] = s; sh_ss[wid] = ss; }
    __syncthreads();
    if (wid == 0) {
        s  = (lid < 8) ? sh_s[lid]  : 0.0f;
        ss = (lid < 8) ? sh_ss[lid] : 0.0f;
        #pragma unroll
        for (int o = 4; o > 0; o >>= 1) {
            s  += __shfl_xor_sync(0xffffffffu, s,  o);
            ss += __shfl_xor_sync(0xffffffffu, ss, o);
        }
        if (lid == 0) { sh_s[0] = s; sh_ss[0] = ss; }
    }
    __syncthreads();
    float mean = sh_s[0] * (1.0f / DIM);
    float var  = sh_ss[0] * (1.0f / DIM) - mean * mean;
    float rstd = rsqrtf(var + 1e-5f);

    const float4 wv = ((const float4*)w)[threadIdx.x];
    const float4 bv = ((const float4*)b)[threadIdx.x];
    uint2 out;
    out.x = packbf((v.x - mean) * rstd * wv.x + bv.x,
                   (v.y - mean) * rstd * wv.y + bv.y);
    out.y = packbf((v.z - mean) * rstd * wv.z + bv.z,
                   (v.w - mean) * rstd * wv.w + bv.w);
    *(uint2*)&g_hw[(size_t)row * DIMW + threadIdx.x * 2] = out;
}

// ---------------- bf16 mma.sync GEMM, double-buffered ------------------------
// MODE 0: A=g_hw, B=g_wq, fused bias + per-head L2 norm, bf16 scatter to q/k/v.
// MODE 1: A=g_ow, B=g_wo, y = C + bias + x (fp32).
__device__ __forceinline__ void scatter2(int m, int n, float v0, float v1) {
    int which = n >> 10;
    int hn = n & 1023;
    int head = hn >> 6, d = hn & 63;
    unsigned* dst = (which == 0) ? g_qw : (which == 1) ? g_kw : g_vw;
    int bb = m >> 11, t = m & 2047;
    dst[(((size_t)(bb * NH + head)) * SEQ + t) * HDW + (d >> 1)] = packbf(v0, v1);
}

template<int MODE>
__global__ __launch_bounds__(256) void gemm_bf(const float* __restrict__ bias,
                                               const float* __restrict__ x,
                                               float* __restrict__ y) {
    const unsigned* Asrc = (MODE == 0) ? g_hw : g_ow;
    const unsigned* Bsrc = (MODE == 0) ? g_wq : g_wo;
    __shared__ unsigned Aw[2][128 * 20];
    __shared__ unsigned Bw[2][128 * 20];

    const int tid = threadIdx.x;
    const int w = tid >> 5, lane = tid & 31;
    const int g = lane >> 2, j = lane & 3;
    const int wm = w & 3, wn = w >> 2;
    const int m0 = blockIdx.y * 128;
    const int n0 = blockIdx.x * 128;

    const unsigned* ag = Asrc + (size_t)m0 * DIMW;
    const unsigned* bg = Bsrc + (size_t)n0 * DIMW;
    const int r0l = tid >> 2, q0l = (tid & 3) * 4;
    const int r1l = (tid + 256) >> 2, q1l = q0l;

    float4 c[2][8];
    #pragma unroll
    for (int mt = 0; mt < 2; mt++)
        #pragma unroll
        for (int nt = 0; nt < 8; nt++) c[mt][nt] = make_float4(0.f, 0.f, 0.f, 0.f);

    uint4 pa0, pa1, pb0, pb1;
    pa0 = *(const uint4*)(ag + (size_t)r0l * DIMW + q0l);
    pa1 = *(const uint4*)(ag + (size_t)r1l * DIMW + q1l);
    pb0 = *(const uint4*)(bg + (size_t)r0l * DIMW + q0l);
    pb1 = *(const uint4*)(bg + (size_t)r1l * DIMW + q1l);
    *(uint4*)&Aw[0][r0l * 20 + q0l] = pa0;
    *(uint4*)&Aw[0][r1l * 20 + q1l] = pa1;
    *(uint4*)&Bw[0][r0l * 20 + q0l] = pb0;
    *(uint4*)&Bw[0][r1l * 20 + q1l] = pb1;
    __syncthreads();

    for (int kt = 0; kt < 32; kt++) {
        const int cur = kt & 1, nxt = cur ^ 1;
        if (kt + 1 < 32) {
            int ko = (kt + 1) * 16;
            pa0 = *(const uint4*)(ag + (size_t)r0l * DIMW + ko + q0l);
            pa1 = *(const uint4*)(ag + (size_t)r1l * DIMW + ko + q1l);
            pb0 = *(const uint4*)(bg + (size_t)r0l * DIMW + ko + q0l);
            pb1 = *(const uint4*)(bg + (size_t)r1l * DIMW + ko + q1l);
        }

        #pragma unroll
        for (int kc = 0; kc < 2; kc++) {
            unsigned a[2][4];
            #pragma unroll
            for (int mt = 0; mt < 2; mt++) {
                int row = wm * 32 + mt * 16 + g;
                a[mt][0] = Aw[cur][row * 20 + kc * 8 + j];
                a[mt][1] = Aw[cur][(row + 8) * 20 + kc * 8 + j];
                a[mt][2] = Aw[cur][row * 20 + kc * 8 + j + 4];
                a[mt][3] = Aw[cur][(row + 8) * 20 + kc * 8 + j + 4];
            }
            unsigned b0[8], b1[8];
            #pragma unroll
            for (int nt = 0; nt < 8; nt++) {
                int n = wn * 64 + nt * 8 + g;
                b0[nt] = Bw[cur][n * 20 + kc * 8 + j];
                b1[nt] = Bw[cur][n * 20 + kc * 8 + j + 4];
            }
            #pragma unroll
            for (int mt = 0; mt < 2; mt++)
                #pragma unroll
                for (int nt = 0; nt < 8; nt++)
                    mmabf(c[mt][nt], a[mt][0], a[mt][1], a[mt][2], a[mt][3],
                          b0[nt], b1[nt]);
        }

        if (kt + 1 < 32) {
            *(uint4*)&Aw[nxt][r0l * 20 + q0l] = pa0;
            *(uint4*)&Aw[nxt][r1l * 20 + q1l] = pa1;
            *(uint4*)&Bw[nxt][r0l * 20 + q0l] = pb0;
            *(uint4*)&Bw[nxt][r1l * 20 + q1l] = pb1;
        }
        __syncthreads();
    }

    if (MODE == 0) {
        // warp's 64-col span = exactly one head; lanes 4g+j form the quad
        const int which = (n0 + wn * 64) >> 10;        // 0=q, 1=k, 2=v
        const float sc = (which == 0) ? QSCALE : 1.0f;
        #pragma unroll
        for (int mt = 0; mt < 2; mt++) {
            int r0 = m0 + wm * 32 + mt * 16 + g;
            int r1 = r0 + 8;
            float v0[16], v1[16];
            float ss0 = 0.f, ss1 = 0.f;
            #pragma unroll
            for (int nt = 0; nt < 8; nt++) {
                int n = n0 + wn * 64 + nt * 8 + 2 * j;
                float bv0 = bias[n], bv1 = bias[n + 1];
                v0[2*nt]   = c[mt][nt].x + bv0;
                v0[2*nt+1] = c[mt][nt].y + bv1;
                v1[2*nt]   = c[mt][nt].z + bv0;
                v1[2*nt+1] = c[mt][nt].w + bv1;
                ss0 += v0[2*nt]*v0[2*nt] + v0[2*nt+1]*v0[2*nt+1];
                ss1 += v1[2*nt]*v1[2*nt] + v1[2*nt+1]*v1[2*nt+1];
            }
            float rn0 = 1.f, rn1 = 1.f;
            if (which < 2) {
                #pragma unroll
                for (int off = 1; off <= 2; off <<= 1) {
                    ss0 += __shfl_xor_sync(0xffffffffu, ss0, off);
                    ss1 += __shfl_xor_sync(0xffffffffu, ss1, off);
                }
                rn0 = sc / fmaxf(sqrtf(ss0), 1e-12f);
                rn1 = sc / fmaxf(sqrtf(ss1), 1e-12f);
            }
            #pragma unroll
            for (int nt = 0; nt < 8; nt++) {
                int n = n0 + wn * 64 + nt * 8 + 2 * j;
                scatter2(r0, n, v0[2*nt] * rn0, v0[2*nt+1] * rn0);
                scatter2(r1, n, v1[2*nt] * rn1, v1[2*nt+1] * rn1);
            }
        }
    } else {
        #pragma unroll
        for (int mt = 0; mt < 2; mt++) {
            int r0 = m0 + wm * 32 + mt * 16 + g;
            int r1 = r0 + 8;
            #pragma unroll
            for (int nt = 0; nt < 8; nt++) {
                int n = n0 + wn * 64 + nt * 8 + 2 * j;
                float bv0 = bias[n], bv1 = bias[n + 1];
                y[(size_t)r0 * DIM + n]     = c[mt][nt].x + bv0 + x[(size_t)r0 * DIM + n];
                y[(size_t)r0 * DIM + n + 1] = c[mt][nt].y + bv1 + x[(size_t)r0 * DIM + n + 1];
                y[(size_t)r1 * DIM + n]     = c[mt][nt].z + bv0 + x[(size_t)r1 * DIM + n];
                y[(size_t)r1 * DIM + n + 1] = c[mt][nt].w + bv1 + x[(size_t)r1 * DIM + n + 1];
            }
        }
    }
}

// ---------------- flash attention: 32 Q rows/warp, fixed-max softmax ---------
// Block = 256 Q rows, 8 warps; warp w owns rows [w*32, w*32+32) as 2 m-tiles.
// K/V B-fragments shared across both m-tiles -> LDS per FLOP halved.
__global__ __launch_bounds__(256, 1) void flash_bf() {
    __shared__ unsigned Ksw[2][64 * 36];   // [buf][key][dim-pair word]
    __shared__ unsigned Vsp[2][32 * 72];   // [buf][key-pair][dim word]

    const int tid = threadIdx.x, w = tid >> 5, lane = tid & 31;
    const int g = lane >> 2, j = lane & 3;
    const int bh = blockIdx.y;
    const int q0 = blockIdx.x * 256;

    const unsigned* qw = g_qw + ((size_t)bh * SEQ + q0) * HDW;
    const unsigned* kw = g_kw + (size_t)bh * SEQ * HDW;
    const unsigned* vw = g_vw + (size_t)bh * SEQ * HDW;

    // persistent Q fragments for 2 m-tiles
    unsigned qa[2][4][4];
    #pragma unroll
    for (int mt = 0; mt < 2; mt++) {
        const unsigned* qr  = qw + (size_t)(w * 32 + mt * 16 + g) * HDW;
        const unsigned* qr8 = qr + 8 * HDW;
        #pragma unroll
        for (int kc = 0; kc < 4; kc++) {
            qa[mt][kc][0] = qr [kc * 8 + j];
            qa[mt][kc][1] = qr8[kc * 8 + j];
            qa[mt][kc][2] = qr [kc * 8 + j + 4];
            qa[mt][kc][3] = qr8[kc * 8 + j + 4];
        }
    }

    const int kn  = tid >> 3, kq = (tid & 7) * 4;
    const int kn2 = (tid + 256) >> 3, kq2 = kq;
    const int vp  = tid >> 4, vc = (tid & 15) * 2;
    const int vp2 = (tid + 256) >> 4, vc2 = vc;

#define STAGE(buf, kt) do {                                                     \
    *(uint4*)&Ksw[buf][kn  * 36 + kq ] =                                        \
        *(const uint4*)&kw[(size_t)((kt) + kn ) * HDW + kq ];                   \
    *(uint4*)&Ksw[buf][kn2 * 36 + kq2] =                                        \
        *(const uint4*)&kw[(size_t)((kt) + kn2) * HDW + kq2];                   \
    {                                                                           \
        uint2 w0 = *(const uint2*)&vw[(size_t)((kt) + 2*vp    ) * HDW + vc ];   \
        uint2 w1 = *(const uint2*)&vw[(size_t)((kt) + 2*vp + 1) * HDW + vc ];   \
        uint4 ov;                                                               \
        ov.x = prmt(w0.x, w1.x, 0x5410u); ov.y = prmt(w0.x, w1.x, 0x7632u);     \
        ov.z = prmt(w0.y, w1.y, 0x5410u); ov.w = prmt(w0.y, w1.y, 0x7632u);     \
        *(uint4*)&Vsp[buf][vp * 72 + vc * 2] = ov;                              \
        w0 = *(const uint2*)&vw[(size_t)((kt) + 2*vp2    ) * HDW + vc2];        \
        w1 = *(const uint2*)&vw[(size_t)((kt) + 2*vp2 + 1) * HDW + vc2];        \
        ov.x = prmt(w0.x, w1.x, 0x5410u); ov.y = prmt(w0.x, w1.x, 0x7632u);     \
        ov.z = prmt(w0.y, w1.y, 0x5410u); ov.w = prmt(w0.y, w1.y, 0x7632u);     \
        *(uint4*)&Vsp[buf][vp2 * 72 + vc2 * 2] = ov;                            \
    }                                                                           \
} while (0)

    float4 o[2][8];
    #pragma unroll
    for (int mt = 0; mt < 2; mt++)
        #pragma unroll
        for (int nt = 0; nt < 8; nt++) o[mt][nt] = make_float4(0.f, 0.f, 0.f, 0.f);
    float l0[2] = {0.f, 0.f}, l1[2] = {0.f, 0.f};

    STAGE(0, 0);
    __syncthreads();

    for (int it = 0; it < SEQ / 64; it++) {
        const int cur = it & 1;
        if (it + 1 < SEQ / 64) STAGE(cur ^ 1, (it + 1) * 64);

        // S = Q @ K^T for both m-tiles; B fragments loaded once
        float4 c[2][8];
        #pragma unroll
        for (int mt = 0; mt < 2; mt++)
            #pragma unroll
            for (int nt = 0; nt < 8; nt++) c[mt][nt] = make_float4(0.f, 0.f, 0.f, 0.f);
        #pragma unroll
        for (int nt = 0; nt < 8; nt++) {
            int kb = (nt * 8 + g) * 36;
            #pragma unroll
            for (int kc = 0; kc < 4; kc++) {
                unsigned b0 = Ksw[cur][kb + kc * 8 + j];
                unsigned b1 = Ksw[cur][kb + kc * 8 + j + 4];
                mmabf(c[0][nt], qa[0][kc][0], qa[0][kc][1], qa[0][kc][2], qa[0][kc][3], b0, b1);
                mmabf(c[1][nt], qa[1][kc][0], qa[1][kc][1], qa[1][kc][2], qa[1][kc][3], b0, b1);
            }
        }

        // fixed-max softmax
        #pragma unroll
        for (int mt = 0; mt < 2; mt++)
            #pragma unroll
            for (int nt = 0; nt < 8; nt++) {
                c[mt][nt].x = ex2(c[mt][nt].x - FIXED_MAX);
                c[mt][nt].y = ex2(c[mt][nt].y - FIXED_MAX);
                c[mt][nt].z = ex2(c[mt][nt].z - FIXED_MAX);
                c[mt][nt].w = ex2(c[mt][nt].w - FIXED_MAX);
                l0[mt] += c[mt][nt].x + c[mt][nt].y;
                l1[mt] += c[mt][nt].z + c[mt][nt].w;
            }

        // O += P @ V, V fragments shared across m-tiles
        #pragma unroll
        for (int kc = 0; kc < 4; kc++) {
            unsigned a00 = packbf(c[0][2*kc].x,   c[0][2*kc].y);
            unsigned a01 = packbf(c[0][2*kc].z,   c[0][2*kc].w);
            unsigned a02 = packbf(c[0][2*kc+1].x, c[0][2*kc+1].y);
            unsigned a03 = packbf(c[0][2*kc+1].z, c[0][2*kc+1].w);
            unsigned a10 = packbf(c[1][2*kc].x,   c[1][2*kc].y);
            unsigned a11 = packbf(c[1][2*kc].z,   c[1][2*kc].w);
            unsigned a12 = packbf(c[1][2*kc+1].x, c[1][2*kc+1].y);
            unsigned a13 = packbf(c[1][2*kc+1].z, c[1][2*kc+1].w);
            int vb0 = (kc * 8 + j) * 72;
            int vb1 = (kc * 8 + j + 4) * 72;
            #pragma unroll
            for (int nt = 0; nt < 8; nt++) {
                unsigned b0 = Vsp[cur][vb0 + nt * 8 + g];
                unsigned b1 = Vsp[cur][vb1 + nt * 8 + g];
                mmabf(o[0][nt], a00, a01, a02, a03, b0, b1);
                mmabf(o[1][nt], a10, a11, a12, a13, b0, b1);
            }
        }
        __syncthreads();
    }

    const int b = bh >> 4, head = bh & 15;
    #pragma unroll
    for (int mt = 0; mt < 2; mt++) {
        float s0 = l0[mt], s1 = l1[mt];
        #pragma unroll
        for (int off = 1; off <= 2; off <<= 1) {
            s0 += __shfl_xor_sync(0xffffffffu, s0, off);
            s1 += __shfl_xor_sync(0xffffffffu, s1, off);
        }
        float inv0 = 1.0f / s0, inv1 = 1.0f / s1;
        size_t row0 = ((size_t)(b * SEQ + q0 + w * 32 + mt * 16 + g)) * DIMW + head * 32;
        size_t row1 = row0 + (size_t)8 * DIMW;
        #pragma unroll
        for (int nt = 0; nt < 8; nt++) {
            g_ow[row0 + nt * 4 + j] = packbf(o[mt][nt].x * inv0, o[mt][nt].y * inv0);
            g_ow[row1 + nt * 4 + j] = packbf(o[mt][nt].z * inv1, o[mt][nt].w * inv1);
        }
    }
#undef STAGE
}

// ---------------- launch -----------------------------------------------------
extern "C" void kernel_launch(void* const* d_in, const int* in_sizes, int n_in,
                              void* d_out, int out_size) {
    const float* x     = (const float*)d_in[0];
    const float* ln_w  = (const float*)d_in[1];
    const float* ln_b  = (const float*)d_in[2];
    const float* qkv_w = (const float*)d_in[3];
    const float* qkv_b = (const float*)d_in[4];
    const float* out_w = (const float*)d_in[5];
    const float* out_b = (const float*)d_in[6];
    float* y = (float*)d_out;

    wconv<<<(N3 * DIMW) / 256, 256>>>(qkv_w, out_w);

    ln_kernel<<<MROWS, 256>>>(x, ln_w, ln_b);

    gemm_bf<0><<<dim3(N3 / 128, MROWS / 128), 256>>>(qkv_b, nullptr, nullptr);

    flash_bf<<<dim3(SEQ / 256, BATCH * NH), 256>>>();

    gemm_bf<1><<<dim3(DIM / 128, MROWS / 128), 256>>>(out_b, x, y);
}

// round 11
// speedup vs baseline: 7.4686x; 1.0584x over previous
#include <cuda_runtime.h>
#include <math.h>
#include <stdint.h>

#define BATCH 4
#define SEQ   2048
#define DIM   1024
#define DIMW  512            // bf16x2 words per row
#define NH    16
#define HD    64
#define HDW   32             // bf16x2 words per head row
#define MROWS (BATCH*SEQ)    // 8192
#define N3    (3*DIM)        // 3072
#define NROWS (BATCH*NH*SEQ) // 131072 head rows

// logit bound in exp2 domain: 8*log2(e) = 11.5416
#define FIXED_MAX 11.6f
#define QSCALE (8.0f * 1.4426950408889634f)

// ---------------- scratch (device globals; referenced ONLY in device code) --
__device__ __align__(16) unsigned g_hw[MROWS * DIMW];        // LN out, bf16x2
__device__ __align__(16) unsigned g_wq[(size_t)N3 * DIMW];   // qkv_w bf16
__device__ __align__(16) unsigned g_wo[(size_t)DIM * DIMW];  // out_w bf16
__device__ __align__(16) unsigned g_qw[(size_t)NROWS * HDW]; // q bf16 [bh][t][dw]
__device__ __align__(16) unsigned g_kw[(size_t)NROWS * HDW];
__device__ __align__(16) unsigned g_vw[(size_t)NROWS * HDW];
__device__ __align__(16) unsigned g_ow[MROWS * DIMW];        // attn out, bf16x2

// ---------------- helpers -----------------------------------------------------
__device__ __forceinline__ unsigned packbf(float lo, float hi) {
    unsigned d;
    asm("cvt.rn.bf16x2.f32 %0, %1, %2;" : "=r"(d) : "f"(hi), "f"(lo));
    return d;
}
__device__ __forceinline__ float ex2(float x) {
    float r;
    asm("ex2.approx.f32 %0, %1;" : "=f"(r) : "f"(x));
    return r;
}
__device__ __forceinline__ unsigned prmt(unsigned a, unsigned b, unsigned s) {
    unsigned d;
    asm("prmt.b32 %0, %1, %2, %3;" : "=r"(d) : "r"(a), "r"(b), "r"(s));
    return d;
}
__device__ __forceinline__ void mmabf(float4& d, unsigned a0, unsigned a1,
                                      unsigned a2, unsigned a3,
                                      unsigned b0, unsigned b1) {
    asm volatile(
        "mma.sync.aligned.m16n8k16.row.col.f32.bf16.bf16.f32 "
        "{%0,%1,%2,%3}, {%4,%5,%6,%7}, {%8,%9}, {%0,%1,%2,%3};\n"
        : "+f"(d.x), "+f"(d.y), "+f"(d.z), "+f"(d.w)
        : "r"(a0), "r"(a1), "r"(a2), "r"(a3), "r"(b0), "r"(b1));
}

// ---------------- weight fp32 -> bf16 conversion (once per call) -------------
__global__ __launch_bounds__(256) void wconv(const float* __restrict__ qkvw,
                                             const float* __restrict__ outw) {
    size_t i = (size_t)blockIdx.x * 256 + threadIdx.x;
    const size_t NQ = (size_t)N3 * DIMW;
    const size_t NO = (size_t)DIM * DIMW;
    if (i < NQ) {
        float2 v = *(const float2*)(qkvw + 2 * i);
        g_wq[i] = packbf(v.x, v.y);
    }
    if (i < NO) {
        float2 v = *(const float2*)(outw + 2 * i);
        g_wo[i] = packbf(v.x, v.y);
    }
}

// ---------------- LayerNorm (fp32 math, bf16 output) ------------------------
__global__ __launch_bounds__(256) void ln_kernel(const float* __restrict__ x,
                                                 const float* __restrict__ w,
                                                 const float* __restrict__ b) {
    int row = blockIdx.x;
    const float4 v = ((const float4*)(x + (size_t)row * DIM))[threadIdx.x];
    float s  = v.x + v.y + v.z + v.w;
    float ss = v.x*v.x + v.y*v.y + v.z*v.z + v.w*v.w;

    __shared__ float sh_s[8], sh_ss[8];
    #pragma unroll
    for (int o = 16; o > 0; o >>= 1) {
        s  += __shfl_xor_sync(0xffffffffu, s,  o);
        ss += __shfl_xor_sync(0xffffffffu, ss, o);
    }
    int wid = threadIdx.x >> 5, lid = threadIdx.x & 31;
    if (lid == 0) { sh_s[wid] = s; sh_ss[wid] = ss; }
    __syncthreads();
    if (wid == 0) {
        s  = (lid < 8) ? sh_s[lid]  : 0.0f;
        ss = (lid < 8) ? sh_ss[lid] : 0.0f;
        #pragma unroll
        for (int o = 4; o > 0; o >>= 1) {
            s  += __shfl_xor_sync(0xffffffffu, s,  o);
            ss += __shfl_xor_sync(0xffffffffu, ss, o);
        }
        if (lid == 0) { sh_s[0] = s; sh_ss[0] = ss; }
    }
    __syncthreads();
    float mean = sh_s[0] * (1.0f / DIM);
    float var  = sh_ss[0] * (1.0f / DIM) - mean * mean;
    float rstd = rsqrtf(var + 1e-5f);

    const float4 wv = ((const float4*)w)[threadIdx.x];
    const float4 bv = ((const float4*)b)[threadIdx.x];
    uint2 out;
    out.x = packbf((v.x - mean) * rstd * wv.x + bv.x,
                   (v.y - mean) * rstd * wv.y + bv.y);
    out.y = packbf((v.z - mean) * rstd * wv.z + bv.z,
                   (v.w - mean) * rstd * wv.w + bv.w);
    *(uint2*)&g_hw[(size_t)row * DIMW + threadIdx.x * 2] = out;
}

// ---------------- bf16 mma.sync GEMM, double-buffered ------------------------
// MODE 0: A=g_hw, B=g_wq, fused bias + per-head L2 norm, bf16 scatter to q/k/v.
// MODE 1: A=g_ow, B=g_wo, y = C + bias + x (fp32).
__device__ __forceinline__ void scatter2(int m, int n, float v0, float v1) {
    int which = n >> 10;
    int hn = n & 1023;
    int head = hn >> 6, d = hn & 63;
    unsigned* dst = (which == 0) ? g_qw : (which == 1) ? g_kw : g_vw;
    int bb = m >> 11, t = m & 2047;
    dst[(((size_t)(bb * NH + head)) * SEQ + t) * HDW + (d >> 1)] = packbf(v0, v1);
}

template<int MODE>
__global__ __launch_bounds__(256) void gemm_bf(const float* __restrict__ bias,
                                               const float* __restrict__ x,
                                               float* __restrict__ y) {
    const unsigned* Asrc = (MODE == 0) ? g_hw : g_ow;
    const unsigned* Bsrc = (MODE == 0) ? g_wq : g_wo;
    __shared__ unsigned Aw[2][128 * 20];
    __shared__ unsigned Bw[2][128 * 20];

    const int tid = threadIdx.x;
    const int w = tid >> 5, lane = tid & 31;
    const int g = lane >> 2, j = lane & 3;
    const int wm = w & 3, wn = w >> 2;
    const int m0 = blockIdx.y * 128;
    const int n0 = blockIdx.x * 128;

    const unsigned* ag = Asrc + (size_t)m0 * DIMW;
    const unsigned* bg = Bsrc + (size_t)n0 * DIMW;
    const int r0l = tid >> 2, q0l = (tid & 3) * 4;
    const int r1l = (tid + 256) >> 2, q1l = q0l;

    float4 c[2][8];
    #pragma unroll
    for (int mt = 0; mt < 2; mt++)
        #pragma unroll
        for (int nt = 0; nt < 8; nt++) c[mt][nt] = make_float4(0.f, 0.f, 0.f, 0.f);

    uint4 pa0, pa1, pb0, pb1;
    pa0 = *(const uint4*)(ag + (size_t)r0l * DIMW + q0l);
    pa1 = *(const uint4*)(ag + (size_t)r1l * DIMW + q1l);
    pb0 = *(const uint4*)(bg + (size_t)r0l * DIMW + q0l);
    pb1 = *(const uint4*)(bg + (size_t)r1l * DIMW + q1l);
    *(uint4*)&Aw[0][r0l * 20 + q0l] = pa0;
    *(uint4*)&Aw[0][r1l * 20 + q1l] = pa1;
    *(uint4*)&Bw[0][r0l * 20 + q0l] = pb0;
    *(uint4*)&Bw[0][r1l * 20 + q1l] = pb1;
    __syncthreads();

    for (int kt = 0; kt < 32; kt++) {
        const int cur = kt & 1, nxt = cur ^ 1;
        if (kt + 1 < 32) {
            int ko = (kt + 1) * 16;
            pa0 = *(const uint4*)(ag + (size_t)r0l * DIMW + ko + q0l);
            pa1 = *(const uint4*)(ag + (size_t)r1l * DIMW + ko + q1l);
            pb0 = *(const uint4*)(bg + (size_t)r0l * DIMW + ko + q0l);
            pb1 = *(const uint4*)(bg + (size_t)r1l * DIMW + ko + q1l);
        }

        #pragma unroll
        for (int kc = 0; kc < 2; kc++) {
            unsigned a[2][4];
            #pragma unroll
            for (int mt = 0; mt < 2; mt++) {
                int row = wm * 32 + mt * 16 + g;
                a[mt][0] = Aw[cur][row * 20 + kc * 8 + j];
                a[mt][1] = Aw[cur][(row + 8) * 20 + kc * 8 + j];
                a[mt][2] = Aw[cur][row * 20 + kc * 8 + j + 4];
                a[mt][3] = Aw[cur][(row + 8) * 20 + kc * 8 + j + 4];
            }
            unsigned b0[8], b1[8];
            #pragma unroll
            for (int nt = 0; nt < 8; nt++) {
                int n = wn * 64 + nt * 8 + g;
                b0[nt] = Bw[cur][n * 20 + kc * 8 + j];
                b1[nt] = Bw[cur][n * 20 + kc * 8 + j + 4];
            }
            #pragma unroll
            for (int mt = 0; mt < 2; mt++)
                #pragma unroll
                for (int nt = 0; nt < 8; nt++)
                    mmabf(c[mt][nt], a[mt][0], a[mt][1], a[mt][2], a[mt][3],
                          b0[nt], b1[nt]);
        }

        if (kt + 1 < 32) {
            *(uint4*)&Aw[nxt][r0l * 20 + q0l] = pa0;
            *(uint4*)&Aw[nxt][r1l * 20 + q1l] = pa1;
            *(uint4*)&Bw[nxt][r0l * 20 + q0l] = pb0;
            *(uint4*)&Bw[nxt][r1l * 20 + q1l] = pb1;
        }
        __syncthreads();
    }

    if (MODE == 0) {
        // warp's 64-col span = exactly one head; lanes 4g+j form the quad
        const int which = (n0 + wn * 64) >> 10;        // 0=q, 1=k, 2=v
        const float sc = (which == 0) ? QSCALE : 1.0f;
        #pragma unroll
        for (int mt = 0; mt < 2; mt++) {
            int r0 = m0 + wm * 32 + mt * 16 + g;
            int r1 = r0 + 8;
            float v0[16], v1[16];
            float ss0 = 0.f, ss1 = 0.f;
            #pragma unroll
            for (int nt = 0; nt < 8; nt++) {
                int n = n0 + wn * 64 + nt * 8 + 2 * j;
                float bv0 = bias[n], bv1 = bias[n + 1];
                v0[2*nt]   = c[mt][nt].x + bv0;
                v0[2*nt+1] = c[mt][nt].y + bv1;
                v1[2*nt]   = c[mt][nt].z + bv0;
                v1[2*nt+1] = c[mt][nt].w + bv1;
                ss0 += v0[2*nt]*v0[2*nt] + v0[2*nt+1]*v0[2*nt+1];
                ss1 += v1[2*nt]*v1[2*nt] + v1[2*nt+1]*v1[2*nt+1];
            }
            float rn0 = 1.f, rn1 = 1.f;
            if (which < 2) {
                #pragma unroll
                for (int off = 1; off <= 2; off <<= 1) {
                    ss0 += __shfl_xor_sync(0xffffffffu, ss0, off);
                    ss1 += __shfl_xor_sync(0xffffffffu, ss1, off);
                }
                rn0 = sc / fmaxf(sqrtf(ss0), 1e-12f);
                rn1 = sc / fmaxf(sqrtf(ss1), 1e-12f);
            }
            #pragma unroll
            for (int nt = 0; nt < 8; nt++) {
                int n = n0 + wn * 64 + nt * 8 + 2 * j;
                scatter2(r0, n, v0[2*nt] * rn0, v0[2*nt+1] * rn0);
                scatter2(r1, n, v1[2*nt] * rn1, v1[2*nt+1] * rn1);
            }
        }
    } else {
        #pragma unroll
        for (int mt = 0; mt < 2; mt++) {
            int r0 = m0 + wm * 32 + mt * 16 + g;
            int r1 = r0 + 8;
            #pragma unroll
            for (int nt = 0; nt < 8; nt++) {
                int n = n0 + wn * 64 + nt * 8 + 2 * j;
                float bv0 = bias[n], bv1 = bias[n + 1];
                y[(size_t)r0 * DIM + n]     = c[mt][nt].x + bv0 + x[(size_t)r0 * DIM + n];
                y[(size_t)r0 * DIM + n + 1] = c[mt][nt].y + bv1 + x[(size_t)r0 * DIM + n + 1];
                y[(size_t)r1 * DIM + n]     = c[mt][nt].z + bv0 + x[(size_t)r1 * DIM + n];
                y[(size_t)r1 * DIM + n + 1] = c[mt][nt].w + bv1 + x[(size_t)r1 * DIM + n + 1];
            }
        }
    }
}

// ---------------- flash attention: 16 Q rows/warp, 2 CTAs/SM -----------------
// Block = 128 Q rows, 8 warps; warp w owns rows [w*16, w*16+16).
// __launch_bounds__(256, 2): regs capped 128 -> 2 independent CTAs per SM,
// 4 warps/SMSP with decoupled barriers (tensor/MUFU phases interleave).
__global__ __launch_bounds__(256, 2) void flash_bf() {
    __shared__ unsigned Ksw[2][64 * 36];   // [buf][key][dim-pair word]
    __shared__ unsigned Vsp[2][32 * 72];   // [buf][key-pair][dim word]

    const int tid = threadIdx.x, w = tid >> 5, lane = tid & 31;
    const int g = lane >> 2, j = lane & 3;
    const int bh = blockIdx.y;
    const int q0 = blockIdx.x * 128;

    const unsigned* qw = g_qw + ((size_t)bh * SEQ + q0) * HDW;
    const unsigned* kw = g_kw + (size_t)bh * SEQ * HDW;
    const unsigned* vw = g_vw + (size_t)bh * SEQ * HDW;

    // persistent Q fragments: direct bf16x2 word loads
    unsigned qa[4][4];
    {
        const unsigned* qr  = qw + (size_t)(w * 16 + g) * HDW;
        const unsigned* qr8 = qr + 8 * HDW;
        #pragma unroll
        for (int kc = 0; kc < 4; kc++) {
            qa[kc][0] = qr [kc * 8 + j];
            qa[kc][1] = qr8[kc * 8 + j];
            qa[kc][2] = qr [kc * 8 + j + 4];
            qa[kc][3] = qr8[kc * 8 + j + 4];
        }
    }

    const int kn  = tid >> 3, kq = (tid & 7) * 4;
    const int kn2 = (tid + 256) >> 3, kq2 = kq;
    const int vp  = tid >> 4, vc = (tid & 15) * 2;
    const int vp2 = (tid + 256) >> 4, vc2 = vc;

#define STAGE(buf, kt) do {                                                     \
    *(uint4*)&Ksw[buf][kn  * 36 + kq ] =                                        \
        *(const uint4*)&kw[(size_t)((kt) + kn ) * HDW + kq ];                   \
    *(uint4*)&Ksw[buf][kn2 * 36 + kq2] =                                        \
        *(const uint4*)&kw[(size_t)((kt) + kn2) * HDW + kq2];                   \
    {                                                                           \
        uint2 w0 = *(const uint2*)&vw[(size_t)((kt) + 2*vp    ) * HDW + vc ];   \
        uint2 w1 = *(const uint2*)&vw[(size_t)((kt) + 2*vp + 1) * HDW + vc ];   \
        uint4 ov;                                                               \
        ov.x = prmt(w0.x, w1.x, 0x5410u); ov.y = prmt(w0.x, w1.x, 0x7632u);     \
        ov.z = prmt(w0.y, w1.y, 0x5410u); ov.w = prmt(w0.y, w1.y, 0x7632u);     \
        *(uint4*)&Vsp[buf][vp * 72 + vc * 2] = ov;                              \
        w0 = *(const uint2*)&vw[(size_t)((kt) + 2*vp2    ) * HDW + vc2];        \
        w1 = *(const uint2*)&vw[(size_t)((kt) + 2*vp2 + 1) * HDW + vc2];        \
        ov.x = prmt(w0.x, w1.x, 0x5410u); ov.y = prmt(w0.x, w1.x, 0x7632u);     \
        ov.z = prmt(w0.y, w1.y, 0x5410u); ov.w = prmt(w0.y, w1.y, 0x7632u);     \
        *(uint4*)&Vsp[buf][vp2 * 72 + vc2 * 2] = ov;                            \
    }                                                                           \
} while (0)

    float4 o[8];
    #pragma unroll
    for (int nt = 0; nt < 8; nt++) o[nt] = make_float4(0.f, 0.f, 0.f, 0.f);
    float l0 = 0.f, l1 = 0.f;

    STAGE(0, 0);
    __syncthreads();

    for (int it = 0; it < SEQ / 64; it++) {
        const int cur = it & 1;
        if (it + 1 < SEQ / 64) STAGE(cur ^ 1, (it + 1) * 64);

        // S = Q @ K^T
        float4 c[8];
        #pragma unroll
        for (int nt = 0; nt < 8; nt++) c[nt] = make_float4(0.f, 0.f, 0.f, 0.f);
        #pragma unroll
        for (int nt = 0; nt < 8; nt++) {
            int kb = (nt * 8 + g) * 36;
            #pragma unroll
            for (int kc = 0; kc < 4; kc++) {
                unsigned b0 = Ksw[cur][kb + kc * 8 + j];
                unsigned b1 = Ksw[cur][kb + kc * 8 + j + 4];
                mmabf(c[nt], qa[kc][0], qa[kc][1], qa[kc][2], qa[kc][3], b0, b1);
            }
        }

        // fixed-max softmax: P = exp2(s - C); l accumulates per-thread
        #pragma unroll
        for (int nt = 0; nt < 8; nt++) {
            c[nt].x = ex2(c[nt].x - FIXED_MAX);
            c[nt].y = ex2(c[nt].y - FIXED_MAX);
            c[nt].z = ex2(c[nt].z - FIXED_MAX);
            c[nt].w = ex2(c[nt].w - FIXED_MAX);
            l0 += c[nt].x + c[nt].y;
            l1 += c[nt].z + c[nt].w;
        }

        // O += P @ V (P C-frags pack straight into A-frags)
        #pragma unroll
        for (int kc = 0; kc < 4; kc++) {
            unsigned a0 = packbf(c[2*kc].x,   c[2*kc].y);
            unsigned a1 = packbf(c[2*kc].z,   c[2*kc].w);
            unsigned a2 = packbf(c[2*kc+1].x, c[2*kc+1].y);
            unsigned a3 = packbf(c[2*kc+1].z, c[2*kc+1].w);
            int vb0 = (kc * 8 + j) * 72;
            int vb1 = (kc * 8 + j + 4) * 72;
            #pragma unroll
            for (int nt = 0; nt < 8; nt++) {
                unsigned b0 = Vsp[cur][vb0 + nt * 8 + g];
                unsigned b1 = Vsp[cur][vb1 + nt * 8 + g];
                mmabf(o[nt], a0, a1, a2, a3, b0, b1);
            }
        }
        __syncthreads();
    }

    // one l reduction for the whole kernel (quad lanes share a row)
    #pragma unroll
    for (int off = 1; off <= 2; off <<= 1) {
        l0 += __shfl_xor_sync(0xffffffffu, l0, off);
        l1 += __shfl_xor_sync(0xffffffffu, l1, off);
    }
    float inv0 = 1.0f / l0, inv1 = 1.0f / l1;

    const int b = bh >> 4, head = bh & 15;
    size_t row0 = ((size_t)(b * SEQ + q0 + w * 16 + g)) * DIMW + head * 32;
    size_t row1 = row0 + (size_t)8 * DIMW;
    #pragma unroll
    for (int nt = 0; nt < 8; nt++) {
        g_ow[row0 + nt * 4 + j] = packbf(o[nt].x * inv0, o[nt].y * inv0);
        g_ow[row1 + nt * 4 + j] = packbf(o[nt].z * inv1, o[nt].w * inv1);
    }
#undef STAGE
}

// ---------------- launch -----------------------------------------------------
extern "C" void kernel_launch(void* const* d_in, const int* in_sizes, int n_in,
                              void* d_out, int out_size) {
    const float* x     = (const float*)d_in[0];
    const float* ln_w  = (const float*)d_in[1];
    const float* ln_b  = (const float*)d_in[2];
    const float* qkv_w = (const float*)d_in[3];
    const float* qkv_b = (const float*)d_in[4];
    const float* out_w = (const float*)d_in[5];
    const float* out_b = (const float*)d_in[6];
    float* y = (float*)d_out;

    wconv<<<(N3 * DIMW) / 256, 256>>>(qkv_w, out_w);

    ln_kernel<<<MROWS, 256>>>(x, ln_w, ln_b);

    gemm_bf<0><<<dim3(N3 / 128, MROWS / 128), 256>>>(qkv_b, nullptr, nullptr);

    flash_bf<<<dim3(SEQ / 128, BATCH * NH), 256>>>();

    gemm_bf<1><<<dim3(DIM / 128, MROWS / 128), 256>>>(out_b, x, y);
}